// round 7
// baseline (speedup 1.0000x reference)
#include <cuda_runtime.h>
#include <cstdint>
#include <math.h>

// Shapes: B=64, D=4096, H=32, HKV=8, DH=128, W=2048, G=4
typedef unsigned long long u64;

// ------------------------------------------------------------------
// Scratch (device globals; no allocation allowed)
// ------------------------------------------------------------------
__device__ float g_qkv_part[16 * 64 * 6144];  // split-K partials, fused QKV
__device__ float g_q[64 * 4096];              // q after RoPE (scaled by 1/sqrt(DH))
__device__ float g_knew[64 * 1024];           // k_new after RoPE
__device__ float g_vnew[64 * 1024];
__device__ float g_attn[64 * 4096];           // attention output (pre W_o)
__device__ float g_opart[16 * 64 * 4096];     // split-K partials, O proj
__device__ float g_obuf[64 * 4096];           // out = attn @ W_o^T
__device__ float g_gpart[32 * 64 * 4096];     // split-K partials, gate
__device__ float g_rc[64];                    // RoPE cos table (fp64-exact)
__device__ float g_rs[64];                    // RoPE sin table
// split-KV attention partials: [b*8+kh][split(4)][g(4)][128]
__device__ float g_pout[64 * 8 * 4 * 4 * 128];
__device__ float g_pm[64 * 8 * 4 * 4];        // local max
__device__ float g_ps[64 * 8 * 4 * 4];        // local exp-sum

// ------------------------------------------------------------------
// packed f32x2 helpers
// ------------------------------------------------------------------
__device__ __forceinline__ u64 pk2(float x, float y) {
    u64 r; asm("mov.b64 %0, {%1, %2};" : "=l"(r) : "f"(x), "f"(y)); return r;
}
__device__ __forceinline__ void upk2(u64 v, float& x, float& y) {
    asm("mov.b64 {%0, %1}, %2;" : "=f"(x), "=f"(y) : "l"(v));
}
__device__ __forceinline__ u64 ffma2(u64 a, u64 b, u64 c) {
    u64 d; asm("fma.rn.f32x2 %0, %1, %2, %3;" : "=l"(d) : "l"(a), "l"(b), "l"(c)); return d;
}

// ------------------------------------------------------------------
// GEMM v2 (unchanged from round 5): C[64,N] = A[64,Ktot] @ B[N,Ktot]^T
// ------------------------------------------------------------------
__global__ __launch_bounds__(256, 2) void gemm_v2(
    int mode, const float* __restrict__ x,
    const float* __restrict__ B0, const float* __restrict__ B1, const float* __restrict__ B2,
    int KtotB, int N, int Kc)
{
    __shared__ float As[2][16][68];
    __shared__ float Bs[2][16][260];

    const int tid = threadIdx.x;
    const int n0  = blockIdx.x * 256;
    const int sp  = blockIdx.y;
    const int kb  = sp * Kc;

    const float* Abase;
    int koff = kb;
    if (mode == 0) Abase = x;
    else if (mode == 1) Abase = g_attn;
    else { if (kb < 4096) Abase = x; else { Abase = g_obuf; koff = kb - 4096; } }

    const float* Bb = B0;
    int nr = n0;
    if (mode == 0 && n0 >= 4096) {
        if (n0 < 5120) { Bb = B1; nr = n0 - 4096; }
        else           { Bb = B2; nr = n0 - 5120; }
    }

    float* Cp = (mode == 0) ? g_qkv_part : (mode == 1) ? g_opart : g_gpart;

    const int lr  = tid >> 2;
    const int lk4 = (tid & 3) << 2;
    const float* arow  = Abase + (size_t)lr * 4096 + koff + lk4;
    const float* brow0 = Bb + (size_t)(nr + lr +   0) * KtotB + kb + lk4;
    const float* brow1 = Bb + (size_t)(nr + lr +  64) * KtotB + kb + lk4;
    const float* brow2 = Bb + (size_t)(nr + lr + 128) * KtotB + kb + lk4;
    const float* brow3 = Bb + (size_t)(nr + lr + 192) * KtotB + kb + lk4;

    const int m0 = (tid >> 5) << 3;
    const int nA = (tid & 31) << 2;
    const int nB = nA + 128;

    u64 cA[8][2], cB[8][2];
#pragma unroll
    for (int m = 0; m < 8; m++) { cA[m][0]=0; cA[m][1]=0; cB[m][0]=0; cB[m][1]=0; }

    const int T = Kc >> 4;
    float4 av, bv0, bv1, bv2, bv3;

    av  = *(const float4*)(arow);
    bv0 = *(const float4*)(brow0);
    bv1 = *(const float4*)(brow1);
    bv2 = *(const float4*)(brow2);
    bv3 = *(const float4*)(brow3);
    As[0][lk4+0][lr]=av.x; As[0][lk4+1][lr]=av.y; As[0][lk4+2][lr]=av.z; As[0][lk4+3][lr]=av.w;
    Bs[0][lk4+0][lr    ]=bv0.x; Bs[0][lk4+1][lr    ]=bv0.y; Bs[0][lk4+2][lr    ]=bv0.z; Bs[0][lk4+3][lr    ]=bv0.w;
    Bs[0][lk4+0][lr+ 64]=bv1.x; Bs[0][lk4+1][lr+ 64]=bv1.y; Bs[0][lk4+2][lr+ 64]=bv1.z; Bs[0][lk4+3][lr+ 64]=bv1.w;
    Bs[0][lk4+0][lr+128]=bv2.x; Bs[0][lk4+1][lr+128]=bv2.y; Bs[0][lk4+2][lr+128]=bv2.z; Bs[0][lk4+3][lr+128]=bv2.w;
    Bs[0][lk4+0][lr+192]=bv3.x; Bs[0][lk4+1][lr+192]=bv3.y; Bs[0][lk4+2][lr+192]=bv3.z; Bs[0][lk4+3][lr+192]=bv3.w;
    __syncthreads();

    for (int t = 0; t < T; t++) {
        const int cur = t & 1;
        if (t + 1 < T) {
            const int ko = (t + 1) << 4;
            av  = *(const float4*)(arow  + ko);
            bv0 = *(const float4*)(brow0 + ko);
            bv1 = *(const float4*)(brow1 + ko);
            bv2 = *(const float4*)(brow2 + ko);
            bv3 = *(const float4*)(brow3 + ko);
        }
#pragma unroll
        for (int k = 0; k < 16; k++) {
            ulonglong2 bA  = *(const ulonglong2*)&Bs[cur][k][nA];
            ulonglong2 bBv = *(const ulonglong2*)&Bs[cur][k][nB];
            float4 a0 = *(const float4*)&As[cur][k][m0];
            float4 a1 = *(const float4*)&As[cur][k][m0 + 4];
            u64 s;
            s = pk2(a0.x, a0.x);
            cA[0][0]=ffma2(s,bA.x,cA[0][0]); cA[0][1]=ffma2(s,bA.y,cA[0][1]);
            cB[0][0]=ffma2(s,bBv.x,cB[0][0]); cB[0][1]=ffma2(s,bBv.y,cB[0][1]);
            s = pk2(a0.y, a0.y);
            cA[1][0]=ffma2(s,bA.x,cA[1][0]); cA[1][1]=ffma2(s,bA.y,cA[1][1]);
            cB[1][0]=ffma2(s,bBv.x,cB[1][0]); cB[1][1]=ffma2(s,bBv.y,cB[1][1]);
            s = pk2(a0.z, a0.z);
            cA[2][0]=ffma2(s,bA.x,cA[2][0]); cA[2][1]=ffma2(s,bA.y,cA[2][1]);
            cB[2][0]=ffma2(s,bBv.x,cB[2][0]); cB[2][1]=ffma2(s,bBv.y,cB[2][1]);
            s = pk2(a0.w, a0.w);
            cA[3][0]=ffma2(s,bA.x,cA[3][0]); cA[3][1]=ffma2(s,bA.y,cA[3][1]);
            cB[3][0]=ffma2(s,bBv.x,cB[3][0]); cB[3][1]=ffma2(s,bBv.y,cB[3][1]);
            s = pk2(a1.x, a1.x);
            cA[4][0]=ffma2(s,bA.x,cA[4][0]); cA[4][1]=ffma2(s,bA.y,cA[4][1]);
            cB[4][0]=ffma2(s,bBv.x,cB[4][0]); cB[4][1]=ffma2(s,bBv.y,cB[4][1]);
            s = pk2(a1.y, a1.y);
            cA[5][0]=ffma2(s,bA.x,cA[5][0]); cA[5][1]=ffma2(s,bA.y,cA[5][1]);
            cB[5][0]=ffma2(s,bBv.x,cB[5][0]); cB[5][1]=ffma2(s,bBv.y,cB[5][1]);
            s = pk2(a1.z, a1.z);
            cA[6][0]=ffma2(s,bA.x,cA[6][0]); cA[6][1]=ffma2(s,bA.y,cA[6][1]);
            cB[6][0]=ffma2(s,bBv.x,cB[6][0]); cB[6][1]=ffma2(s,bBv.y,cB[6][1]);
            s = pk2(a1.w, a1.w);
            cA[7][0]=ffma2(s,bA.x,cA[7][0]); cA[7][1]=ffma2(s,bA.y,cA[7][1]);
            cB[7][0]=ffma2(s,bBv.x,cB[7][0]); cB[7][1]=ffma2(s,bBv.y,cB[7][1]);
        }
        if (t + 1 < T) {
            const int nb = cur ^ 1;
            As[nb][lk4+0][lr]=av.x; As[nb][lk4+1][lr]=av.y; As[nb][lk4+2][lr]=av.z; As[nb][lk4+3][lr]=av.w;
            Bs[nb][lk4+0][lr    ]=bv0.x; Bs[nb][lk4+1][lr    ]=bv0.y; Bs[nb][lk4+2][lr    ]=bv0.z; Bs[nb][lk4+3][lr    ]=bv0.w;
            Bs[nb][lk4+0][lr+ 64]=bv1.x; Bs[nb][lk4+1][lr+ 64]=bv1.y; Bs[nb][lk4+2][lr+ 64]=bv1.z; Bs[nb][lk4+3][lr+ 64]=bv1.w;
            Bs[nb][lk4+0][lr+128]=bv2.x; Bs[nb][lk4+1][lr+128]=bv2.y; Bs[nb][lk4+2][lr+128]=bv2.z; Bs[nb][lk4+3][lr+128]=bv2.w;
            Bs[nb][lk4+0][lr+192]=bv3.x; Bs[nb][lk4+1][lr+192]=bv3.y; Bs[nb][lk4+2][lr+192]=bv3.z; Bs[nb][lk4+3][lr+192]=bv3.w;
            __syncthreads();
        }
    }

    {
        float* base = Cp + ((size_t)sp * 64) * N + n0;
#pragma unroll
        for (int m = 0; m < 8; m++) {
            float f0, f1, f2, f3;
            upk2(cA[m][0], f0, f1); upk2(cA[m][1], f2, f3);
            *(float4*)(base + (size_t)(m0 + m) * N + nA) = make_float4(f0, f1, f2, f3);
            upk2(cB[m][0], f0, f1); upk2(cB[m][1], f2, f3);
            *(float4*)(base + (size_t)(m0 + m) * N + nB) = make_float4(f0, f1, f2, f3);
        }
    }
}

// ------------------------------------------------------------------
// RoPE table: 64 (cos,sin) pairs at fp64 accuracy, computed once.
// ------------------------------------------------------------------
__global__ void rope_tab(const int* __restrict__ posp)
{
    int i = threadIdx.x;   // 0..63
    int praw = *posp;
    int pos = praw;
    if (pos < 0 || pos > (1 << 26)) {
        float pf = __int_as_float(praw);
        pos = (int)pf;
    }
    double inv = pow(10000.0, -(double)(2 * i) / 128.0);
    double sn, cn;
    sincos((double)pos * inv, &sn, &cn);
    g_rc[i] = (float)cn;
    g_rs[i] = (float)sn;
}

// ------------------------------------------------------------------
// Reduce QKV split-K partials (16) + RoPE (table lookup).
// ------------------------------------------------------------------
__global__ __launch_bounds__(256) void reduce_qkv_rope()
{
    int idx = blockIdx.x * 256 + threadIdx.x;    // pair index, < 196608
    int b = idx / 3072;
    int col = (idx - b * 3072) * 2;

    const float* p = g_qkv_part + (size_t)b * 6144 + col;
    float s0 = 0.f, s1 = 0.f;
#pragma unroll
    for (int s = 0; s < 16; s++) {
        s0 += p[(size_t)s * 64 * 6144];
        s1 += p[(size_t)s * 64 * 6144 + 1];
    }

    const float qscale = 0.08838834764831845f;   // 1/sqrt(128)

    if (col < 5120) {
        int di = (col & 127) >> 1;
        float c = g_rc[di], s = g_rs[di];
        float o0 = s0 * c - s1 * s;
        float o1 = s0 * s + s1 * c;
        if (col < 4096) {
            g_q[(size_t)b * 4096 + col]     = o0 * qscale;
            g_q[(size_t)b * 4096 + col + 1] = o1 * qscale;
        } else {
            g_knew[(size_t)b * 1024 + (col - 4096)]     = o0;
            g_knew[(size_t)b * 1024 + (col - 4096) + 1] = o1;
        }
    } else {
        g_vnew[(size_t)b * 1024 + (col - 5120)]     = s0;
        g_vnew[(size_t)b * 1024 + (col - 5120) + 1] = s1;
    }
}

// ------------------------------------------------------------------
// Split-KV attention: grid (64 b, 8 kh, 4 splits), 8 warps/block.
// Each split handles 512 keys (64 per warp) with a LOCAL softmax;
// partials (unnormalized out, max, exp-sum) go to scratch.
// Effective key w -> cache slot w+1 for w<2047, k_new/v_new at w=2047.
// ------------------------------------------------------------------
__global__ __launch_bounds__(256) void attn_split(
    const float* __restrict__ kc, const float* __restrict__ vc)
{
    __shared__ float sc[4 * 512];     // local scores [g][512]
    __shared__ float outp[8 * 512];   // warp partials [warp][g][128]
    __shared__ float red[8];
    __shared__ float s_m[4];
    __shared__ float s_s[4];

    const int b    = blockIdx.x;
    const int kh   = blockIdx.y;
    const int spl  = blockIdx.z;
    const int warp = threadIdx.x >> 5;
    const int lane = threadIdx.x & 31;
    const unsigned FULL = 0xffffffffu;

    const float* qp = g_q + (size_t)b * 4096 + kh * 512;   // pre-scaled
    float4 q0 = *(const float4*)(qp + 0 * 128 + lane * 4);
    float4 q1 = *(const float4*)(qp + 1 * 128 + lane * 4);
    float4 q2 = *(const float4*)(qp + 2 * 128 + lane * 4);
    float4 q3 = *(const float4*)(qp + 3 * 128 + lane * 4);

    const size_t bh = (size_t)(b * 8 + kh);
    const float* kbase = kc + bh * (2048 * 128);
    const float* vbase = vc + bh * (2048 * 128);
    const float* knew  = g_knew + bh * 128;
    const float* vnew  = g_vnew + bh * 128;

    const int base = spl * 512 + warp * 64;   // 64 contiguous keys per warp
    const int lbase = warp * 64;              // local score index base
    const bool lo16 = (lane < 16);
    const bool b8   = (lane & 8) != 0;

    // ---------------- score phase ----------------
    {
        float4 kr[2][8];
#pragma unroll
        for (int u = 0; u < 8; u++) {
            int w = base + u;
            const float* p = (w < 2047) ? (kbase + (size_t)(w + 1) * 128) : knew;
            kr[0][u] = *(const float4*)(p + lane * 4);
        }
        for (int j0 = 0; j0 < 64; j0 += 8) {
            int cur = (j0 >> 3) & 1;
            if (j0 + 8 < 64) {
#pragma unroll
                for (int u = 0; u < 8; u++) {
                    int w = base + j0 + 8 + u;
                    const float* p = (w < 2047) ? (kbase + (size_t)(w + 1) * 128) : knew;
                    kr[cur ^ 1][u] = *(const float4*)(p + lane * 4);
                }
            }
#pragma unroll
            for (int u = 0; u < 8; u++) {
                float4 k4 = kr[cur][u];
                float p0 = q0.x * k4.x + q0.y * k4.y + q0.z * k4.z + q0.w * k4.w;
                float p1 = q1.x * k4.x + q1.y * k4.y + q1.z * k4.z + q1.w * k4.w;
                float p2 = q2.x * k4.x + q2.y * k4.y + q2.z * k4.z + q2.w * k4.w;
                float p3 = q3.x * k4.x + q3.y * k4.y + q3.z * k4.z + q3.w * k4.w;
                // 6-shuffle 4-head reduction
                float xa = lo16 ? p2 : p0;
                float ya = __shfl_xor_sync(FULL, xa, 16);
                float pA = lo16 ? (p0 + ya) : (p2 + ya);
                float xb = lo16 ? p3 : p1;
                float yb = __shfl_xor_sync(FULL, xb, 16);
                float pB = lo16 ? (p1 + yb) : (p3 + yb);
                float xc = b8 ? pA : pB;
                float yc = __shfl_xor_sync(FULL, xc, 8);
                float pC = b8 ? (pB + yc) : (pA + yc);
                pC += __shfl_xor_sync(FULL, pC, 4);
                pC += __shfl_xor_sync(FULL, pC, 2);
                pC += __shfl_xor_sync(FULL, pC, 1);
                if ((lane & 7) == 0) sc[(lane >> 3) * 512 + lbase + j0 + u] = pC;
            }
        }
    }
    __syncthreads();

    // ---------------- local softmax per head ----------------
    for (int g = 0; g < 4; g++) {
        float* row = sc + g * 512;
        float mx = -3.0e38f;
        for (int w = threadIdx.x; w < 512; w += 256) mx = fmaxf(mx, row[w]);
#pragma unroll
        for (int off = 16; off > 0; off >>= 1)
            mx = fmaxf(mx, __shfl_xor_sync(FULL, mx, off));
        if (lane == 0) red[warp] = mx;
        __syncthreads();
        if (threadIdx.x == 0) {
            float m = red[0];
            for (int i = 1; i < 8; i++) m = fmaxf(m, red[i]);
            s_m[g] = m;
        }
        __syncthreads();
        mx = s_m[g];
        float sum = 0.f;
        for (int w = threadIdx.x; w < 512; w += 256) {
            float e = expf(row[w] - mx);
            row[w] = e;
            sum += e;
        }
#pragma unroll
        for (int off = 16; off > 0; off >>= 1)
            sum += __shfl_xor_sync(FULL, sum, off);
        if (lane == 0) red[warp] = sum;
        __syncthreads();
        if (threadIdx.x == 0) {
            float s = 0.f;
            for (int i = 0; i < 8; i++) s += red[i];
            s_s[g] = s;
        }
        __syncthreads();
    }

    // ---------------- p @ V (unnormalized) ----------------
    float4 a0 = make_float4(0, 0, 0, 0), a1 = a0, a2 = a0, a3 = a0;
    {
        float4 vr[2][8];
#pragma unroll
        for (int u = 0; u < 8; u++) {
            int w = base + u;
            const float* p = (w < 2047) ? (vbase + (size_t)(w + 1) * 128) : vnew;
            vr[0][u] = *(const float4*)(p + lane * 4);
        }
        for (int j0 = 0; j0 < 64; j0 += 8) {
            int cur = (j0 >> 3) & 1;
            if (j0 + 8 < 64) {
#pragma unroll
                for (int u = 0; u < 8; u++) {
                    int w = base + j0 + 8 + u;
                    const float* p = (w < 2047) ? (vbase + (size_t)(w + 1) * 128) : vnew;
                    vr[cur ^ 1][u] = *(const float4*)(p + lane * 4);
                }
            }
#pragma unroll
            for (int u = 0; u < 8; u++) {
                int lw = lbase + j0 + u;
                float4 v4 = vr[cur][u];
                float p0 = sc[lw];
                float p1 = sc[512 + lw];
                float p2 = sc[1024 + lw];
                float p3 = sc[1536 + lw];
                a0.x += p0 * v4.x; a0.y += p0 * v4.y; a0.z += p0 * v4.z; a0.w += p0 * v4.w;
                a1.x += p1 * v4.x; a1.y += p1 * v4.y; a1.z += p1 * v4.z; a1.w += p1 * v4.w;
                a2.x += p2 * v4.x; a2.y += p2 * v4.y; a2.z += p2 * v4.z; a2.w += p2 * v4.w;
                a3.x += p3 * v4.x; a3.y += p3 * v4.y; a3.z += p3 * v4.z; a3.w += p3 * v4.w;
            }
        }
    }
    __syncthreads();

    *(float4*)&outp[warp * 512 + 0 * 128 + lane * 4] = a0;
    *(float4*)&outp[warp * 512 + 1 * 128 + lane * 4] = a1;
    *(float4*)&outp[warp * 512 + 2 * 128 + lane * 4] = a2;
    *(float4*)&outp[warp * 512 + 3 * 128 + lane * 4] = a3;
    __syncthreads();

    // write partials
    const size_t pb = (bh * 4 + spl) * 4;   // index into [bh][split][g]
    for (int oi = threadIdx.x; oi < 512; oi += 256) {
        int g = oi >> 7;
        float s = 0.f;
#pragma unroll
        for (int w8 = 0; w8 < 8; w8++) s += outp[w8 * 512 + oi];
        g_pout[(pb + g) * 128 + (oi & 127)] = s;
    }
    if (threadIdx.x < 4) {
        g_pm[pb + threadIdx.x] = s_m[threadIdx.x];
        g_ps[pb + threadIdx.x] = s_s[threadIdx.x];
    }
}

// ------------------------------------------------------------------
// Combine split partials: one thread per output element.
// grid (64, 8), 512 threads.
// ------------------------------------------------------------------
__global__ __launch_bounds__(512) void attn_combine()
{
    const int b  = blockIdx.x;
    const int kh = blockIdx.y;
    const int tid = threadIdx.x;        // 0..511
    const int g = tid >> 7;
    const int d = tid & 127;

    const size_t bh = (size_t)(b * 8 + kh);
    const size_t pb = bh * 16;          // [split(4)][g(4)]

    float m0 = g_pm[pb + 0 * 4 + g];
    float m1 = g_pm[pb + 1 * 4 + g];
    float m2 = g_pm[pb + 2 * 4 + g];
    float m3 = g_pm[pb + 3 * 4 + g];
    float M = fmaxf(fmaxf(m0, m1), fmaxf(m2, m3));
    float w0 = expf(m0 - M), w1 = expf(m1 - M), w2 = expf(m2 - M), w3 = expf(m3 - M);
    float denom = g_ps[pb + 0 * 4 + g] * w0 + g_ps[pb + 1 * 4 + g] * w1
                + g_ps[pb + 2 * 4 + g] * w2 + g_ps[pb + 3 * 4 + g] * w3;
    float val = g_pout[(pb + 0 * 4 + g) * 128 + d] * w0
              + g_pout[(pb + 1 * 4 + g) * 128 + d] * w1
              + g_pout[(pb + 2 * 4 + g) * 128 + d] * w2
              + g_pout[(pb + 3 * 4 + g) * 128 + d] * w3;
    g_attn[bh * 512 + tid] = val / denom;
}

// ------------------------------------------------------------------
// Reduce O split-K partials (16)
// ------------------------------------------------------------------
__global__ __launch_bounds__(256) void reduce_o()
{
    int idx = blockIdx.x * 256 + threadIdx.x;   // < 262144
    float s = 0.f;
#pragma unroll
    for (int sp = 0; sp < 16; sp++) s += g_opart[(size_t)sp * 262144 + idx];
    g_obuf[idx] = s;
}

// ------------------------------------------------------------------
// Reduce gate partials (32) + bias + sigmoid + residual
// ------------------------------------------------------------------
__global__ __launch_bounds__(256) void reduce_gate(
    const float* __restrict__ gb, const float* __restrict__ x, float* __restrict__ out)
{
    int idx = blockIdx.x * 256 + threadIdx.x;   // < 262144
    int i = idx & 4095;
    float s = gb[i];
#pragma unroll
    for (int sp = 0; sp < 32; sp++) s += g_gpart[(size_t)sp * 262144 + idx];
    float g = 1.0f / (1.0f + expf(-s));
    out[idx] = x[idx] + g * g_obuf[idx];
}

// ------------------------------------------------------------------
// Launch
// ------------------------------------------------------------------
extern "C" void kernel_launch(void* const* d_in, const int* in_sizes, int n_in,
                              void* d_out, int out_size)
{
    const float* x  = (const float*)d_in[0];
    const float* kc = (const float*)d_in[1];
    const float* vc = (const float*)d_in[2];
    const float* Wq = (const float*)d_in[3];
    const float* Wk = (const float*)d_in[4];
    const float* Wv = (const float*)d_in[5];
    const float* Wo = (const float*)d_in[6];
    const float* gw = (const float*)d_in[7];
    const float* gb = (const float*)d_in[8];
    const int*   pp = (const int*)d_in[9];
    float* out = (float*)d_out;

    rope_tab<<<1, 64>>>(pp);

    // Fused QKV: n-tiles 24, split-K 16
    gemm_v2<<<dim3(24, 16), 256>>>(0, x, Wq, Wk, Wv, 4096, 6144, 256);
    reduce_qkv_rope<<<768, 256>>>();

    // Split-KV attention + combine
    attn_split<<<dim3(64, 8, 4), 256>>>(kc, vc);
    attn_combine<<<dim3(64, 8), 512>>>();

    // O projection: n-tiles 16, split-K 16
    gemm_v2<<<dim3(16, 16), 256>>>(1, x, Wo, nullptr, nullptr, 4096, 4096, 256);
    reduce_o<<<1024, 256>>>();

    // Gate: n-tiles 16, split-K 32
    gemm_v2<<<dim3(16, 32), 256>>>(2, x, gw, nullptr, nullptr, 8192, 4096, 256);
    reduce_gate<<<1024, 256>>>(gb, x, out);
}

// round 11
// speedup vs baseline: 1.1221x; 1.1221x over previous
#include <cuda_runtime.h>
#include <cstdint>
#include <math.h>

// Shapes: B=64, D=4096, H=32, HKV=8, DH=128, W=2048, G=4
typedef unsigned long long u64;

// ------------------------------------------------------------------
// Scratch (device globals; no allocation allowed)
// ------------------------------------------------------------------
__device__ float g_qkv_part[16 * 64 * 6144];  // split-K partials, fused QKV
__device__ float g_q[64 * 4096];              // q after RoPE (scaled by 1/sqrt(DH))
__device__ float g_knew[64 * 1024];           // k_new after RoPE
__device__ float g_vnew[64 * 1024];
__device__ float g_attn[64 * 4096];           // attention output (pre W_o)
__device__ float g_opart[16 * 64 * 4096];     // split-K partials, O proj
__device__ float g_obuf[64 * 4096];           // out = attn @ W_o^T
__device__ float g_gpart[32 * 64 * 4096];     // split-K partials, gate
__device__ float g_rc[64];                    // RoPE cos table (fp64-exact)
__device__ float g_rs[64];                    // RoPE sin table
// split-KV attention partials: [b*8+kh][split(8)][g(4)][128]
__device__ float g_pout[64 * 8 * 8 * 4 * 128];
__device__ float g_pm[64 * 8 * 8 * 4];        // local max
__device__ float g_ps[64 * 8 * 8 * 4];        // local exp-sum

// ------------------------------------------------------------------
// packed f32x2 helpers
// ------------------------------------------------------------------
__device__ __forceinline__ u64 pk2(float x, float y) {
    u64 r; asm("mov.b64 %0, {%1, %2};" : "=l"(r) : "f"(x), "f"(y)); return r;
}
__device__ __forceinline__ void upk2(u64 v, float& x, float& y) {
    asm("mov.b64 {%0, %1}, %2;" : "=f"(x), "=f"(y) : "l"(v));
}
__device__ __forceinline__ u64 ffma2(u64 a, u64 b, u64 c) {
    u64 d; asm("fma.rn.f32x2 %0, %1, %2, %3;" : "=l"(d) : "l"(a), "l"(b), "l"(c)); return d;
}

// ------------------------------------------------------------------
// GEMM v2 (unchanged): C[64,N] = A[64,Ktot] @ B[N,Ktot]^T
// ------------------------------------------------------------------
__global__ __launch_bounds__(256, 2) void gemm_v2(
    int mode, const float* __restrict__ x,
    const float* __restrict__ B0, const float* __restrict__ B1, const float* __restrict__ B2,
    int KtotB, int N, int Kc)
{
    __shared__ float As[2][16][68];
    __shared__ float Bs[2][16][260];

    const int tid = threadIdx.x;
    const int n0  = blockIdx.x * 256;
    const int sp  = blockIdx.y;
    const int kb  = sp * Kc;

    const float* Abase;
    int koff = kb;
    if (mode == 0) Abase = x;
    else if (mode == 1) Abase = g_attn;
    else { if (kb < 4096) Abase = x; else { Abase = g_obuf; koff = kb - 4096; } }

    const float* Bb = B0;
    int nr = n0;
    if (mode == 0 && n0 >= 4096) {
        if (n0 < 5120) { Bb = B1; nr = n0 - 4096; }
        else           { Bb = B2; nr = n0 - 5120; }
    }

    float* Cp = (mode == 0) ? g_qkv_part : (mode == 1) ? g_opart : g_gpart;

    const int lr  = tid >> 2;
    const int lk4 = (tid & 3) << 2;
    const float* arow  = Abase + (size_t)lr * 4096 + koff + lk4;
    const float* brow0 = Bb + (size_t)(nr + lr +   0) * KtotB + kb + lk4;
    const float* brow1 = Bb + (size_t)(nr + lr +  64) * KtotB + kb + lk4;
    const float* brow2 = Bb + (size_t)(nr + lr + 128) * KtotB + kb + lk4;
    const float* brow3 = Bb + (size_t)(nr + lr + 192) * KtotB + kb + lk4;

    const int m0 = (tid >> 5) << 3;
    const int nA = (tid & 31) << 2;
    const int nB = nA + 128;

    u64 cA[8][2], cB[8][2];
#pragma unroll
    for (int m = 0; m < 8; m++) { cA[m][0]=0; cA[m][1]=0; cB[m][0]=0; cB[m][1]=0; }

    const int T = Kc >> 4;
    float4 av, bv0, bv1, bv2, bv3;

    av  = *(const float4*)(arow);
    bv0 = *(const float4*)(brow0);
    bv1 = *(const float4*)(brow1);
    bv2 = *(const float4*)(brow2);
    bv3 = *(const float4*)(brow3);
    As[0][lk4+0][lr]=av.x; As[0][lk4+1][lr]=av.y; As[0][lk4+2][lr]=av.z; As[0][lk4+3][lr]=av.w;
    Bs[0][lk4+0][lr    ]=bv0.x; Bs[0][lk4+1][lr    ]=bv0.y; Bs[0][lk4+2][lr    ]=bv0.z; Bs[0][lk4+3][lr    ]=bv0.w;
    Bs[0][lk4+0][lr+ 64]=bv1.x; Bs[0][lk4+1][lr+ 64]=bv1.y; Bs[0][lk4+2][lr+ 64]=bv1.z; Bs[0][lk4+3][lr+ 64]=bv1.w;
    Bs[0][lk4+0][lr+128]=bv2.x; Bs[0][lk4+1][lr+128]=bv2.y; Bs[0][lk4+2][lr+128]=bv2.z; Bs[0][lk4+3][lr+128]=bv2.w;
    Bs[0][lk4+0][lr+192]=bv3.x; Bs[0][lk4+1][lr+192]=bv3.y; Bs[0][lk4+2][lr+192]=bv3.z; Bs[0][lk4+3][lr+192]=bv3.w;
    __syncthreads();

    for (int t = 0; t < T; t++) {
        const int cur = t & 1;
        if (t + 1 < T) {
            const int ko = (t + 1) << 4;
            av  = *(const float4*)(arow  + ko);
            bv0 = *(const float4*)(brow0 + ko);
            bv1 = *(const float4*)(brow1 + ko);
            bv2 = *(const float4*)(brow2 + ko);
            bv3 = *(const float4*)(brow3 + ko);
        }
#pragma unroll
        for (int k = 0; k < 16; k++) {
            ulonglong2 bA  = *(const ulonglong2*)&Bs[cur][k][nA];
            ulonglong2 bBv = *(const ulonglong2*)&Bs[cur][k][nB];
            float4 a0 = *(const float4*)&As[cur][k][m0];
            float4 a1 = *(const float4*)&As[cur][k][m0 + 4];
            u64 s;
            s = pk2(a0.x, a0.x);
            cA[0][0]=ffma2(s,bA.x,cA[0][0]); cA[0][1]=ffma2(s,bA.y,cA[0][1]);
            cB[0][0]=ffma2(s,bBv.x,cB[0][0]); cB[0][1]=ffma2(s,bBv.y,cB[0][1]);
            s = pk2(a0.y, a0.y);
            cA[1][0]=ffma2(s,bA.x,cA[1][0]); cA[1][1]=ffma2(s,bA.y,cA[1][1]);
            cB[1][0]=ffma2(s,bBv.x,cB[1][0]); cB[1][1]=ffma2(s,bBv.y,cB[1][1]);
            s = pk2(a0.z, a0.z);
            cA[2][0]=ffma2(s,bA.x,cA[2][0]); cA[2][1]=ffma2(s,bA.y,cA[2][1]);
            cB[2][0]=ffma2(s,bBv.x,cB[2][0]); cB[2][1]=ffma2(s,bBv.y,cB[2][1]);
            s = pk2(a0.w, a0.w);
            cA[3][0]=ffma2(s,bA.x,cA[3][0]); cA[3][1]=ffma2(s,bA.y,cA[3][1]);
            cB[3][0]=ffma2(s,bBv.x,cB[3][0]); cB[3][1]=ffma2(s,bBv.y,cB[3][1]);
            s = pk2(a1.x, a1.x);
            cA[4][0]=ffma2(s,bA.x,cA[4][0]); cA[4][1]=ffma2(s,bA.y,cA[4][1]);
            cB[4][0]=ffma2(s,bBv.x,cB[4][0]); cB[4][1]=ffma2(s,bBv.y,cB[4][1]);
            s = pk2(a1.y, a1.y);
            cA[5][0]=ffma2(s,bA.x,cA[5][0]); cA[5][1]=ffma2(s,bA.y,cA[5][1]);
            cB[5][0]=ffma2(s,bBv.x,cB[5][0]); cB[5][1]=ffma2(s,bBv.y,cB[5][1]);
            s = pk2(a1.z, a1.z);
            cA[6][0]=ffma2(s,bA.x,cA[6][0]); cA[6][1]=ffma2(s,bA.y,cA[6][1]);
            cB[6][0]=ffma2(s,bBv.x,cB[6][0]); cB[6][1]=ffma2(s,bBv.y,cB[6][1]);
            s = pk2(a1.w, a1.w);
            cA[7][0]=ffma2(s,bA.x,cA[7][0]); cA[7][1]=ffma2(s,bA.y,cA[7][1]);
            cB[7][0]=ffma2(s,bBv.x,cB[7][0]); cB[7][1]=ffma2(s,bBv.y,cB[7][1]);
        }
        if (t + 1 < T) {
            const int nb = cur ^ 1;
            As[nb][lk4+0][lr]=av.x; As[nb][lk4+1][lr]=av.y; As[nb][lk4+2][lr]=av.z; As[nb][lk4+3][lr]=av.w;
            Bs[nb][lk4+0][lr    ]=bv0.x; Bs[nb][lk4+1][lr    ]=bv0.y; Bs[nb][lk4+2][lr    ]=bv0.z; Bs[nb][lk4+3][lr    ]=bv0.w;
            Bs[nb][lk4+0][lr+ 64]=bv1.x; Bs[nb][lk4+1][lr+ 64]=bv1.y; Bs[nb][lk4+2][lr+ 64]=bv1.z; Bs[nb][lk4+3][lr+ 64]=bv1.w;
            Bs[nb][lk4+0][lr+128]=bv2.x; Bs[nb][lk4+1][lr+128]=bv2.y; Bs[nb][lk4+2][lr+128]=bv2.z; Bs[nb][lk4+3][lr+128]=bv2.w;
            Bs[nb][lk4+0][lr+192]=bv3.x; Bs[nb][lk4+1][lr+192]=bv3.y; Bs[nb][lk4+2][lr+192]=bv3.z; Bs[nb][lk4+3][lr+192]=bv3.w;
            __syncthreads();
        }
    }

    {
        float* base = Cp + ((size_t)sp * 64) * N + n0;
#pragma unroll
        for (int m = 0; m < 8; m++) {
            float f0, f1, f2, f3;
            upk2(cA[m][0], f0, f1); upk2(cA[m][1], f2, f3);
            *(float4*)(base + (size_t)(m0 + m) * N + nA) = make_float4(f0, f1, f2, f3);
            upk2(cB[m][0], f0, f1); upk2(cB[m][1], f2, f3);
            *(float4*)(base + (size_t)(m0 + m) * N + nB) = make_float4(f0, f1, f2, f3);
        }
    }
}

// ------------------------------------------------------------------
// RoPE table (fp64-exact, once)
// ------------------------------------------------------------------
__global__ void rope_tab(const int* __restrict__ posp)
{
    int i = threadIdx.x;   // 0..63
    int praw = *posp;
    int pos = praw;
    if (pos < 0 || pos > (1 << 26)) {
        float pf = __int_as_float(praw);
        pos = (int)pf;
    }
    double inv = pow(10000.0, -(double)(2 * i) / 128.0);
    double sn, cn;
    sincos((double)pos * inv, &sn, &cn);
    g_rc[i] = (float)cn;
    g_rs[i] = (float)sn;
}

// ------------------------------------------------------------------
// Reduce QKV split-K partials (16) + RoPE (table lookup).
// ------------------------------------------------------------------
__global__ __launch_bounds__(256) void reduce_qkv_rope()
{
    int idx = blockIdx.x * 256 + threadIdx.x;    // pair index, < 196608
    int b = idx / 3072;
    int col = (idx - b * 3072) * 2;

    const float* p = g_qkv_part + (size_t)b * 6144 + col;
    float s0 = 0.f, s1 = 0.f;
#pragma unroll
    for (int s = 0; s < 16; s++) {
        s0 += p[(size_t)s * 64 * 6144];
        s1 += p[(size_t)s * 64 * 6144 + 1];
    }

    const float qscale = 0.08838834764831845f;   // 1/sqrt(128)

    if (col < 5120) {
        int di = (col & 127) >> 1;
        float c = g_rc[di], s = g_rs[di];
        float o0 = s0 * c - s1 * s;
        float o1 = s0 * s + s1 * c;
        if (col < 4096) {
            g_q[(size_t)b * 4096 + col]     = o0 * qscale;
            g_q[(size_t)b * 4096 + col + 1] = o1 * qscale;
        } else {
            g_knew[(size_t)b * 1024 + (col - 4096)]     = o0;
            g_knew[(size_t)b * 1024 + (col - 4096) + 1] = o1;
        }
    } else {
        g_vnew[(size_t)b * 1024 + (col - 5120)]     = s0;
        g_vnew[(size_t)b * 1024 + (col - 5120) + 1] = s1;
    }
}

// ------------------------------------------------------------------
// Split-KV attention v3: grid (64, 8, 8), 128 threads (4 warps).
// 256 keys/CTA, 64/warp in 4-key double-buffered batches.
// Scores stored key-major sc[w][4] -> pV reads 1 broadcast LDS.128.
// Single-pass softmax, thread-per-2-keys. pV in packed f32x2.
// ------------------------------------------------------------------
__global__ __launch_bounds__(128, 8) void attn_split(
    const float* __restrict__ kc, const float* __restrict__ vc)
{
    __shared__ float sc[256 * 4];      // [key][head]
    __shared__ float outp[4 * 512];    // [warp][head][128]
    __shared__ float red_r[4 * 4];     // [warp][head]
    __shared__ float s_m[4];
    __shared__ float s_s[4];

    const int tid  = threadIdx.x;
    const int b    = blockIdx.x;
    const int kh   = blockIdx.y;
    const int spl  = blockIdx.z;
    const int warp = tid >> 5;
    const int lane = tid & 31;
    const unsigned FULL = 0xffffffffu;

    const float* qp = g_q + (size_t)b * 4096 + kh * 512;   // pre-scaled
    float4 q0 = *(const float4*)(qp + 0 * 128 + lane * 4);
    float4 q1 = *(const float4*)(qp + 1 * 128 + lane * 4);
    float4 q2 = *(const float4*)(qp + 2 * 128 + lane * 4);
    float4 q3 = *(const float4*)(qp + 3 * 128 + lane * 4);

    const size_t bh = (size_t)(b * 8 + kh);
    const float* kbase = kc + bh * (2048 * 128);
    const float* vbase = vc + bh * (2048 * 128);
    const float* knew  = g_knew + bh * 128;
    const float* vnew  = g_vnew + bh * 128;

    const int base  = spl * 256 + warp * 64;   // global first key of this warp
    const int lbase = warp * 64;               // local score base
    const bool lo16 = (lane < 16);
    const bool b8   = (lane & 8) != 0;

    // ---------------- score phase ----------------
    {
        float4 kr[2][4];
#pragma unroll
        for (int u = 0; u < 4; u++) {
            int w = base + u;
            const float* p = (w < 2047) ? (kbase + (size_t)(w + 1) * 128) : knew;
            kr[0][u] = *(const float4*)(p + lane * 4);
        }
        for (int j0 = 0; j0 < 64; j0 += 4) {
            int cur = (j0 >> 2) & 1;
            if (j0 + 4 < 64) {
#pragma unroll
                for (int u = 0; u < 4; u++) {
                    int w = base + j0 + 4 + u;
                    const float* p = (w < 2047) ? (kbase + (size_t)(w + 1) * 128) : knew;
                    kr[cur ^ 1][u] = *(const float4*)(p + lane * 4);
                }
            }
#pragma unroll
            for (int u = 0; u < 4; u++) {
                float4 k4 = kr[cur][u];
                float p0 = q0.x * k4.x + q0.y * k4.y + q0.z * k4.z + q0.w * k4.w;
                float p1 = q1.x * k4.x + q1.y * k4.y + q1.z * k4.z + q1.w * k4.w;
                float p2 = q2.x * k4.x + q2.y * k4.y + q2.z * k4.z + q2.w * k4.w;
                float p3 = q3.x * k4.x + q3.y * k4.y + q3.z * k4.z + q3.w * k4.w;
                // 6-shuffle 4-head reduction
                float xa = lo16 ? p2 : p0;
                float ya = __shfl_xor_sync(FULL, xa, 16);
                float pA = lo16 ? (p0 + ya) : (p2 + ya);
                float xb = lo16 ? p3 : p1;
                float yb = __shfl_xor_sync(FULL, xb, 16);
                float pB = lo16 ? (p1 + yb) : (p3 + yb);
                float xc = b8 ? pA : pB;
                float yc = __shfl_xor_sync(FULL, xc, 8);
                float pC = b8 ? (pB + yc) : (pA + yc);
                pC += __shfl_xor_sync(FULL, pC, 4);
                pC += __shfl_xor_sync(FULL, pC, 2);
                pC += __shfl_xor_sync(FULL, pC, 1);
                // lanes 0,8,16,24 hold heads 0..3; store key-major
                if ((lane & 7) == 0) sc[(lbase + j0 + u) * 4 + (lane >> 3)] = pC;
            }
        }
    }
    __syncthreads();

    // ---------------- single-pass local softmax ----------------
    {
        const int k0 = tid * 2;            // thread owns keys k0, k0+1
        float4 v0 = *(const float4*)&sc[k0 * 4];
        float4 v1 = *(const float4*)&sc[k0 * 4 + 4];
        float m0 = fmaxf(v0.x, v1.x), m1 = fmaxf(v0.y, v1.y);
        float m2 = fmaxf(v0.z, v1.z), m3 = fmaxf(v0.w, v1.w);
#pragma unroll
        for (int off = 16; off > 0; off >>= 1) {
            m0 = fmaxf(m0, __shfl_xor_sync(FULL, m0, off));
            m1 = fmaxf(m1, __shfl_xor_sync(FULL, m1, off));
            m2 = fmaxf(m2, __shfl_xor_sync(FULL, m2, off));
            m3 = fmaxf(m3, __shfl_xor_sync(FULL, m3, off));
        }
        if (lane == 0) {
            red_r[warp * 4 + 0] = m0; red_r[warp * 4 + 1] = m1;
            red_r[warp * 4 + 2] = m2; red_r[warp * 4 + 3] = m3;
        }
        __syncthreads();
        if (tid < 4) {
            float m = red_r[tid];
            for (int w = 1; w < 4; w++) m = fmaxf(m, red_r[w * 4 + tid]);
            s_m[tid] = m;
        }
        __syncthreads();
        float M0 = s_m[0], M1 = s_m[1], M2 = s_m[2], M3 = s_m[3];
        float e00 = expf(v0.x - M0), e01 = expf(v0.y - M1);
        float e02 = expf(v0.z - M2), e03 = expf(v0.w - M3);
        float e10 = expf(v1.x - M0), e11 = expf(v1.y - M1);
        float e12 = expf(v1.z - M2), e13 = expf(v1.w - M3);
        *(float4*)&sc[k0 * 4]     = make_float4(e00, e01, e02, e03);
        *(float4*)&sc[k0 * 4 + 4] = make_float4(e10, e11, e12, e13);
        float t0 = e00 + e10, t1 = e01 + e11, t2 = e02 + e12, t3 = e03 + e13;
#pragma unroll
        for (int off = 16; off > 0; off >>= 1) {
            t0 += __shfl_xor_sync(FULL, t0, off);
            t1 += __shfl_xor_sync(FULL, t1, off);
            t2 += __shfl_xor_sync(FULL, t2, off);
            t3 += __shfl_xor_sync(FULL, t3, off);
        }
        if (lane == 0) {
            red_r[warp * 4 + 0] = t0; red_r[warp * 4 + 1] = t1;
            red_r[warp * 4 + 2] = t2; red_r[warp * 4 + 3] = t3;
        }
        __syncthreads();
        if (tid < 4) {
            float s = red_r[tid];
            for (int w = 1; w < 4; w++) s += red_r[w * 4 + tid];
            s_s[tid] = s;
        }
        __syncthreads();
    }

    // ---------------- p @ V (unnormalized, packed f32x2) ----------------
    u64 ap0 = 0, ap1 = 0, ap2 = 0, ap3 = 0, ap4 = 0, ap5 = 0, ap6 = 0, ap7 = 0;
    {
        float4 vr[2][4];
#pragma unroll
        for (int u = 0; u < 4; u++) {
            int w = base + u;
            const float* p = (w < 2047) ? (vbase + (size_t)(w + 1) * 128) : vnew;
            vr[0][u] = *(const float4*)(p + lane * 4);
        }
        for (int j0 = 0; j0 < 64; j0 += 4) {
            int cur = (j0 >> 2) & 1;
            if (j0 + 4 < 64) {
#pragma unroll
                for (int u = 0; u < 4; u++) {
                    int w = base + j0 + 4 + u;
                    const float* p = (w < 2047) ? (vbase + (size_t)(w + 1) * 128) : vnew;
                    vr[cur ^ 1][u] = *(const float4*)(p + lane * 4);
                }
            }
#pragma unroll
            for (int u = 0; u < 4; u++) {
                float4 v4 = vr[cur][u];
                float4 pv = *(const float4*)&sc[(lbase + j0 + u) * 4];  // broadcast
                u64 vx = pk2(v4.x, v4.y);
                u64 vz = pk2(v4.z, v4.w);
                u64 pp;
                pp = pk2(pv.x, pv.x); ap0 = ffma2(pp, vx, ap0); ap1 = ffma2(pp, vz, ap1);
                pp = pk2(pv.y, pv.y); ap2 = ffma2(pp, vx, ap2); ap3 = ffma2(pp, vz, ap3);
                pp = pk2(pv.z, pv.z); ap4 = ffma2(pp, vx, ap4); ap5 = ffma2(pp, vz, ap5);
                pp = pk2(pv.w, pv.w); ap6 = ffma2(pp, vx, ap6); ap7 = ffma2(pp, vz, ap7);
            }
        }
    }

    // unpack accumulators to smem: outp[warp][head][128]
    {
        float f0, f1, f2, f3;
        upk2(ap0, f0, f1); upk2(ap1, f2, f3);
        *(float4*)&outp[warp * 512 + 0 * 128 + lane * 4] = make_float4(f0, f1, f2, f3);
        upk2(ap2, f0, f1); upk2(ap3, f2, f3);
        *(float4*)&outp[warp * 512 + 1 * 128 + lane * 4] = make_float4(f0, f1, f2, f3);
        upk2(ap4, f0, f1); upk2(ap5, f2, f3);
        *(float4*)&outp[warp * 512 + 2 * 128 + lane * 4] = make_float4(f0, f1, f2, f3);
        upk2(ap6, f0, f1); upk2(ap7, f2, f3);
        *(float4*)&outp[warp * 512 + 3 * 128 + lane * 4] = make_float4(f0, f1, f2, f3);
    }
    __syncthreads();

    // write partials: [bh][split][g][128]
    const size_t pb = (bh * 8 + spl) * 4;
    for (int oi = tid; oi < 512; oi += 128) {
        float s = outp[oi] + outp[512 + oi] + outp[1024 + oi] + outp[1536 + oi];
        g_pout[(pb + (oi >> 7)) * 128 + (oi & 127)] = s;
    }
    if (tid < 4) {
        g_pm[pb + tid] = s_m[tid];
        g_ps[pb + tid] = s_s[tid];
    }
}

// ------------------------------------------------------------------
// Combine 8 split partials. grid (64, 8), 512 threads.
// ------------------------------------------------------------------
__global__ __launch_bounds__(512) void attn_combine()
{
    const int b  = blockIdx.x;
    const int kh = blockIdx.y;
    const int tid = threadIdx.x;        // 0..511
    const int g = tid >> 7;
    const int d = tid & 127;

    const size_t bh = (size_t)(b * 8 + kh);
    const size_t pb = bh * 32;          // [split(8)][g(4)]

    float m[8];
#pragma unroll
    for (int s = 0; s < 8; s++) m[s] = g_pm[pb + s * 4 + g];
    float M = m[0];
#pragma unroll
    for (int s = 1; s < 8; s++) M = fmaxf(M, m[s]);
    float denom = 0.f, val = 0.f;
#pragma unroll
    for (int s = 0; s < 8; s++) {
        float w = expf(m[s] - M);
        denom += g_ps[pb + s * 4 + g] * w;
        val   += g_pout[(pb + s * 4 + g) * 128 + d] * w;
    }
    g_attn[bh * 512 + tid] = val / denom;
}

// ------------------------------------------------------------------
// Reduce O split-K partials (16)
// ------------------------------------------------------------------
__global__ __launch_bounds__(256) void reduce_o()
{
    int idx = blockIdx.x * 256 + threadIdx.x;   // < 262144
    float s = 0.f;
#pragma unroll
    for (int sp = 0; sp < 16; sp++) s += g_opart[(size_t)sp * 262144 + idx];
    g_obuf[idx] = s;
}

// ------------------------------------------------------------------
// Reduce gate partials (32) + bias + sigmoid + residual
// ------------------------------------------------------------------
__global__ __launch_bounds__(256) void reduce_gate(
    const float* __restrict__ gb, const float* __restrict__ x, float* __restrict__ out)
{
    int idx = blockIdx.x * 256 + threadIdx.x;   // < 262144
    int i = idx & 4095;
    float s = gb[i];
#pragma unroll
    for (int sp = 0; sp < 32; sp++) s += g_gpart[(size_t)sp * 262144 + idx];
    float g = 1.0f / (1.0f + expf(-s));
    out[idx] = x[idx] + g * g_obuf[idx];
}

// ------------------------------------------------------------------
// Launch
// ------------------------------------------------------------------
extern "C" void kernel_launch(void* const* d_in, const int* in_sizes, int n_in,
                              void* d_out, int out_size)
{
    const float* x  = (const float*)d_in[0];
    const float* kc = (const float*)d_in[1];
    const float* vc = (const float*)d_in[2];
    const float* Wq = (const float*)d_in[3];
    const float* Wk = (const float*)d_in[4];
    const float* Wv = (const float*)d_in[5];
    const float* Wo = (const float*)d_in[6];
    const float* gw = (const float*)d_in[7];
    const float* gb = (const float*)d_in[8];
    const int*   pp = (const int*)d_in[9];
    float* out = (float*)d_out;

    rope_tab<<<1, 64>>>(pp);

    // Fused QKV: n-tiles 24, split-K 16
    gemm_v2<<<dim3(24, 16), 256>>>(0, x, Wq, Wk, Wv, 4096, 6144, 256);
    reduce_qkv_rope<<<768, 256>>>();

    // Split-KV attention (8 splits) + combine
    attn_split<<<dim3(64, 8, 8), 128>>>(kc, vc);
    attn_combine<<<dim3(64, 8), 512>>>();

    // O projection: n-tiles 16, split-K 16
    gemm_v2<<<dim3(16, 16), 256>>>(1, x, Wo, nullptr, nullptr, 4096, 4096, 256);
    reduce_o<<<1024, 256>>>();

    // Gate: n-tiles 16, split-K 32
    gemm_v2<<<dim3(16, 32), 256>>>(2, x, gw, nullptr, nullptr, 8192, 4096, 256);
    reduce_gate<<<1024, 256>>>(gb, x, out);
}

// round 13
// speedup vs baseline: 1.1898x; 1.0604x over previous
#include <cuda_runtime.h>
#include <cstdint>
#include <math.h>

// Shapes: B=64, D=4096, H=32, HKV=8, DH=128, W=2048, G=4
typedef unsigned long long u64;

// ------------------------------------------------------------------
// Scratch (device globals; no allocation allowed)
// ------------------------------------------------------------------
__device__ float g_qkv_part[16 * 64 * 6144];  // split-K partials, fused QKV
__device__ float g_q[64 * 4096];              // q after RoPE (scaled by 1/sqrt(DH))
__device__ float g_knew[64 * 1024];           // k_new after RoPE
__device__ float g_vnew[64 * 1024];
__device__ float g_attn[64 * 4096];           // attention output (pre W_o)
__device__ float g_opart[16 * 64 * 4096];     // split-K partials, O proj
__device__ float g_obuf[64 * 4096];           // out = attn @ W_o^T
__device__ float g_gpart[32 * 64 * 4096];     // split-K partials, gate
__device__ float g_rc[64];                    // RoPE cos table (fp64-exact)
__device__ float g_rs[64];                    // RoPE sin table
// split-KV attention partials: [b*8+kh][split(8)][g(4)][128]
__device__ float g_pout[64 * 8 * 8 * 4 * 128];
__device__ float g_pm[64 * 8 * 8 * 4];        // local max
__device__ float g_ps[64 * 8 * 8 * 4];        // local exp-sum

// ------------------------------------------------------------------
// packed f32x2 helpers
// ------------------------------------------------------------------
__device__ __forceinline__ u64 pk2(float x, float y) {
    u64 r; asm("mov.b64 %0, {%1, %2};" : "=l"(r) : "f"(x), "f"(y)); return r;
}
__device__ __forceinline__ void upk2(u64 v, float& x, float& y) {
    asm("mov.b64 {%0, %1}, %2;" : "=f"(x), "=f"(y) : "l"(v));
}
__device__ __forceinline__ u64 ffma2(u64 a, u64 b, u64 c) {
    u64 d; asm("fma.rn.f32x2 %0, %1, %2, %3;" : "=l"(d) : "l"(a), "l"(b), "l"(c)); return d;
}

// ------------------------------------------------------------------
// GEMM v2 (unchanged): C[64,N] = A[64,Ktot] @ B[N,Ktot]^T
// ------------------------------------------------------------------
__global__ __launch_bounds__(256, 2) void gemm_v2(
    int mode, const float* __restrict__ x,
    const float* __restrict__ B0, const float* __restrict__ B1, const float* __restrict__ B2,
    int KtotB, int N, int Kc)
{
    __shared__ float As[2][16][68];
    __shared__ float Bs[2][16][260];

    const int tid = threadIdx.x;
    const int n0  = blockIdx.x * 256;
    const int sp  = blockIdx.y;
    const int kb  = sp * Kc;

    const float* Abase;
    int koff = kb;
    if (mode == 0) Abase = x;
    else if (mode == 1) Abase = g_attn;
    else { if (kb < 4096) Abase = x; else { Abase = g_obuf; koff = kb - 4096; } }

    const float* Bb = B0;
    int nr = n0;
    if (mode == 0 && n0 >= 4096) {
        if (n0 < 5120) { Bb = B1; nr = n0 - 4096; }
        else           { Bb = B2; nr = n0 - 5120; }
    }

    float* Cp = (mode == 0) ? g_qkv_part : (mode == 1) ? g_opart : g_gpart;

    const int lr  = tid >> 2;
    const int lk4 = (tid & 3) << 2;
    const float* arow  = Abase + (size_t)lr * 4096 + koff + lk4;
    const float* brow0 = Bb + (size_t)(nr + lr +   0) * KtotB + kb + lk4;
    const float* brow1 = Bb + (size_t)(nr + lr +  64) * KtotB + kb + lk4;
    const float* brow2 = Bb + (size_t)(nr + lr + 128) * KtotB + kb + lk4;
    const float* brow3 = Bb + (size_t)(nr + lr + 192) * KtotB + kb + lk4;

    const int m0 = (tid >> 5) << 3;
    const int nA = (tid & 31) << 2;
    const int nB = nA + 128;

    u64 cA[8][2], cB[8][2];
#pragma unroll
    for (int m = 0; m < 8; m++) { cA[m][0]=0; cA[m][1]=0; cB[m][0]=0; cB[m][1]=0; }

    const int T = Kc >> 4;
    float4 av, bv0, bv1, bv2, bv3;

    av  = *(const float4*)(arow);
    bv0 = *(const float4*)(brow0);
    bv1 = *(const float4*)(brow1);
    bv2 = *(const float4*)(brow2);
    bv3 = *(const float4*)(brow3);
    As[0][lk4+0][lr]=av.x; As[0][lk4+1][lr]=av.y; As[0][lk4+2][lr]=av.z; As[0][lk4+3][lr]=av.w;
    Bs[0][lk4+0][lr    ]=bv0.x; Bs[0][lk4+1][lr    ]=bv0.y; Bs[0][lk4+2][lr    ]=bv0.z; Bs[0][lk4+3][lr    ]=bv0.w;
    Bs[0][lk4+0][lr+ 64]=bv1.x; Bs[0][lk4+1][lr+ 64]=bv1.y; Bs[0][lk4+2][lr+ 64]=bv1.z; Bs[0][lk4+3][lr+ 64]=bv1.w;
    Bs[0][lk4+0][lr+128]=bv2.x; Bs[0][lk4+1][lr+128]=bv2.y; Bs[0][lk4+2][lr+128]=bv2.z; Bs[0][lk4+3][lr+128]=bv2.w;
    Bs[0][lk4+0][lr+192]=bv3.x; Bs[0][lk4+1][lr+192]=bv3.y; Bs[0][lk4+2][lr+192]=bv3.z; Bs[0][lk4+3][lr+192]=bv3.w;
    __syncthreads();

    for (int t = 0; t < T; t++) {
        const int cur = t & 1;
        if (t + 1 < T) {
            const int ko = (t + 1) << 4;
            av  = *(const float4*)(arow  + ko);
            bv0 = *(const float4*)(brow0 + ko);
            bv1 = *(const float4*)(brow1 + ko);
            bv2 = *(const float4*)(brow2 + ko);
            bv3 = *(const float4*)(brow3 + ko);
        }
#pragma unroll
        for (int k = 0; k < 16; k++) {
            ulonglong2 bA  = *(const ulonglong2*)&Bs[cur][k][nA];
            ulonglong2 bBv = *(const ulonglong2*)&Bs[cur][k][nB];
            float4 a0 = *(const float4*)&As[cur][k][m0];
            float4 a1 = *(const float4*)&As[cur][k][m0 + 4];
            u64 s;
            s = pk2(a0.x, a0.x);
            cA[0][0]=ffma2(s,bA.x,cA[0][0]); cA[0][1]=ffma2(s,bA.y,cA[0][1]);
            cB[0][0]=ffma2(s,bBv.x,cB[0][0]); cB[0][1]=ffma2(s,bBv.y,cB[0][1]);
            s = pk2(a0.y, a0.y);
            cA[1][0]=ffma2(s,bA.x,cA[1][0]); cA[1][1]=ffma2(s,bA.y,cA[1][1]);
            cB[1][0]=ffma2(s,bBv.x,cB[1][0]); cB[1][1]=ffma2(s,bBv.y,cB[1][1]);
            s = pk2(a0.z, a0.z);
            cA[2][0]=ffma2(s,bA.x,cA[2][0]); cA[2][1]=ffma2(s,bA.y,cA[2][1]);
            cB[2][0]=ffma2(s,bBv.x,cB[2][0]); cB[2][1]=ffma2(s,bBv.y,cB[2][1]);
            s = pk2(a0.w, a0.w);
            cA[3][0]=ffma2(s,bA.x,cA[3][0]); cA[3][1]=ffma2(s,bA.y,cA[3][1]);
            cB[3][0]=ffma2(s,bBv.x,cB[3][0]); cB[3][1]=ffma2(s,bBv.y,cB[3][1]);
            s = pk2(a1.x, a1.x);
            cA[4][0]=ffma2(s,bA.x,cA[4][0]); cA[4][1]=ffma2(s,bA.y,cA[4][1]);
            cB[4][0]=ffma2(s,bBv.x,cB[4][0]); cB[4][1]=ffma2(s,bBv.y,cB[4][1]);
            s = pk2(a1.y, a1.y);
            cA[5][0]=ffma2(s,bA.x,cA[5][0]); cA[5][1]=ffma2(s,bA.y,cA[5][1]);
            cB[5][0]=ffma2(s,bBv.x,cB[5][0]); cB[5][1]=ffma2(s,bBv.y,cB[5][1]);
            s = pk2(a1.z, a1.z);
            cA[6][0]=ffma2(s,bA.x,cA[6][0]); cA[6][1]=ffma2(s,bA.y,cA[6][1]);
            cB[6][0]=ffma2(s,bBv.x,cB[6][0]); cB[6][1]=ffma2(s,bBv.y,cB[6][1]);
            s = pk2(a1.w, a1.w);
            cA[7][0]=ffma2(s,bA.x,cA[7][0]); cA[7][1]=ffma2(s,bA.y,cA[7][1]);
            cB[7][0]=ffma2(s,bBv.x,cB[7][0]); cB[7][1]=ffma2(s,bBv.y,cB[7][1]);
        }
        if (t + 1 < T) {
            const int nb = cur ^ 1;
            As[nb][lk4+0][lr]=av.x; As[nb][lk4+1][lr]=av.y; As[nb][lk4+2][lr]=av.z; As[nb][lk4+3][lr]=av.w;
            Bs[nb][lk4+0][lr    ]=bv0.x; Bs[nb][lk4+1][lr    ]=bv0.y; Bs[nb][lk4+2][lr    ]=bv0.z; Bs[nb][lk4+3][lr    ]=bv0.w;
            Bs[nb][lk4+0][lr+ 64]=bv1.x; Bs[nb][lk4+1][lr+ 64]=bv1.y; Bs[nb][lk4+2][lr+ 64]=bv1.z; Bs[nb][lk4+3][lr+ 64]=bv1.w;
            Bs[nb][lk4+0][lr+128]=bv2.x; Bs[nb][lk4+1][lr+128]=bv2.y; Bs[nb][lk4+2][lr+128]=bv2.z; Bs[nb][lk4+3][lr+128]=bv2.w;
            Bs[nb][lk4+0][lr+192]=bv3.x; Bs[nb][lk4+1][lr+192]=bv3.y; Bs[nb][lk4+2][lr+192]=bv3.z; Bs[nb][lk4+3][lr+192]=bv3.w;
            __syncthreads();
        }
    }

    {
        float* base = Cp + ((size_t)sp * 64) * N + n0;
#pragma unroll
        for (int m = 0; m < 8; m++) {
            float f0, f1, f2, f3;
            upk2(cA[m][0], f0, f1); upk2(cA[m][1], f2, f3);
            *(float4*)(base + (size_t)(m0 + m) * N + nA) = make_float4(f0, f1, f2, f3);
            upk2(cB[m][0], f0, f1); upk2(cB[m][1], f2, f3);
            *(float4*)(base + (size_t)(m0 + m) * N + nB) = make_float4(f0, f1, f2, f3);
        }
    }
}

// ------------------------------------------------------------------
// RoPE table (fp64-exact, once)
// ------------------------------------------------------------------
__global__ void rope_tab(const int* __restrict__ posp)
{
    int i = threadIdx.x;   // 0..63
    int praw = *posp;
    int pos = praw;
    if (pos < 0 || pos > (1 << 26)) {
        float pf = __int_as_float(praw);
        pos = (int)pf;
    }
    double inv = pow(10000.0, -(double)(2 * i) / 128.0);
    double sn, cn;
    sincos((double)pos * inv, &sn, &cn);
    g_rc[i] = (float)cn;
    g_rs[i] = (float)sn;
}

// ------------------------------------------------------------------
// Reduce QKV split-K partials (16) + RoPE (table lookup).
// ------------------------------------------------------------------
__global__ __launch_bounds__(256) void reduce_qkv_rope()
{
    int idx = blockIdx.x * 256 + threadIdx.x;    // pair index, < 196608
    int b = idx / 3072;
    int col = (idx - b * 3072) * 2;

    const float* p = g_qkv_part + (size_t)b * 6144 + col;
    float s0 = 0.f, s1 = 0.f;
#pragma unroll
    for (int s = 0; s < 16; s++) {
        s0 += p[(size_t)s * 64 * 6144];
        s1 += p[(size_t)s * 64 * 6144 + 1];
    }

    const float qscale = 0.08838834764831845f;   // 1/sqrt(128)

    if (col < 5120) {
        int di = (col & 127) >> 1;
        float c = g_rc[di], s = g_rs[di];
        float o0 = s0 * c - s1 * s;
        float o1 = s0 * s + s1 * c;
        if (col < 4096) {
            g_q[(size_t)b * 4096 + col]     = o0 * qscale;
            g_q[(size_t)b * 4096 + col + 1] = o1 * qscale;
        } else {
            g_knew[(size_t)b * 1024 + (col - 4096)]     = o0;
            g_knew[(size_t)b * 1024 + (col - 4096) + 1] = o1;
        }
    } else {
        g_vnew[(size_t)b * 1024 + (col - 5120)]     = s0;
        g_vnew[(size_t)b * 1024 + (col - 5120) + 1] = s1;
    }
}

// ------------------------------------------------------------------
// Split-KV attention v4: grid (64, 8, 8), 128 threads (4 warps).
// 256 keys/CTA, 64/warp in 2-key double-buffered batches (16-reg bufs)
// + __launch_bounds__(128,10) -> 40 warps/SM residency.
// Scores stored key-major sc[w][4]; pV reads 1 broadcast LDS.128.
// ------------------------------------------------------------------
__global__ __launch_bounds__(128, 10) void attn_split(
    const float* __restrict__ kc, const float* __restrict__ vc)
{
    __shared__ float sc[256 * 4];      // [key][head]
    __shared__ float outp[4 * 512];    // [warp][head][128]
    __shared__ float red_r[4 * 4];     // [warp][head]
    __shared__ float s_m[4];
    __shared__ float s_s[4];

    const int tid  = threadIdx.x;
    const int b    = blockIdx.x;
    const int kh   = blockIdx.y;
    const int spl  = blockIdx.z;
    const int warp = tid >> 5;
    const int lane = tid & 31;
    const unsigned FULL = 0xffffffffu;

    const float* qp = g_q + (size_t)b * 4096 + kh * 512;   // pre-scaled
    float4 q0 = *(const float4*)(qp + 0 * 128 + lane * 4);
    float4 q1 = *(const float4*)(qp + 1 * 128 + lane * 4);
    float4 q2 = *(const float4*)(qp + 2 * 128 + lane * 4);
    float4 q3 = *(const float4*)(qp + 3 * 128 + lane * 4);

    const size_t bh = (size_t)(b * 8 + kh);
    const float* kbase = kc + bh * (2048 * 128);
    const float* vbase = vc + bh * (2048 * 128);
    const float* knew  = g_knew + bh * 128;
    const float* vnew  = g_vnew + bh * 128;

    const int base  = spl * 256 + warp * 64;   // global first key of this warp
    const int lbase = warp * 64;               // local score base
    const bool lo16 = (lane < 16);
    const bool b8   = (lane & 8) != 0;

    // ---------------- score phase (2-key double-buffered) ----------------
    {
        float4 kr[2][2];
#pragma unroll
        for (int u = 0; u < 2; u++) {
            int w = base + u;
            const float* p = (w < 2047) ? (kbase + (size_t)(w + 1) * 128) : knew;
            kr[0][u] = *(const float4*)(p + lane * 4);
        }
        for (int j0 = 0; j0 < 64; j0 += 2) {
            int cur = (j0 >> 1) & 1;
            if (j0 + 2 < 64) {
#pragma unroll
                for (int u = 0; u < 2; u++) {
                    int w = base + j0 + 2 + u;
                    const float* p = (w < 2047) ? (kbase + (size_t)(w + 1) * 128) : knew;
                    kr[cur ^ 1][u] = *(const float4*)(p + lane * 4);
                }
            }
#pragma unroll
            for (int u = 0; u < 2; u++) {
                float4 k4 = kr[cur][u];
                float p0 = q0.x * k4.x + q0.y * k4.y + q0.z * k4.z + q0.w * k4.w;
                float p1 = q1.x * k4.x + q1.y * k4.y + q1.z * k4.z + q1.w * k4.w;
                float p2 = q2.x * k4.x + q2.y * k4.y + q2.z * k4.z + q2.w * k4.w;
                float p3 = q3.x * k4.x + q3.y * k4.y + q3.z * k4.z + q3.w * k4.w;
                // 6-shuffle 4-head reduction
                float xa = lo16 ? p2 : p0;
                float ya = __shfl_xor_sync(FULL, xa, 16);
                float pA = lo16 ? (p0 + ya) : (p2 + ya);
                float xb = lo16 ? p3 : p1;
                float yb = __shfl_xor_sync(FULL, xb, 16);
                float pB = lo16 ? (p1 + yb) : (p3 + yb);
                float xc = b8 ? pA : pB;
                float yc = __shfl_xor_sync(FULL, xc, 8);
                float pC = b8 ? (pB + yc) : (pA + yc);
                pC += __shfl_xor_sync(FULL, pC, 4);
                pC += __shfl_xor_sync(FULL, pC, 2);
                pC += __shfl_xor_sync(FULL, pC, 1);
                // lanes 0,8,16,24 hold heads 0..3; store key-major
                if ((lane & 7) == 0) sc[(lbase + j0 + u) * 4 + (lane >> 3)] = pC;
            }
        }
    }
    __syncthreads();

    // ---------------- single-pass local softmax ----------------
    {
        const int k0 = tid * 2;            // thread owns keys k0, k0+1
        float4 v0 = *(const float4*)&sc[k0 * 4];
        float4 v1 = *(const float4*)&sc[k0 * 4 + 4];
        float m0 = fmaxf(v0.x, v1.x), m1 = fmaxf(v0.y, v1.y);
        float m2 = fmaxf(v0.z, v1.z), m3 = fmaxf(v0.w, v1.w);
#pragma unroll
        for (int off = 16; off > 0; off >>= 1) {
            m0 = fmaxf(m0, __shfl_xor_sync(FULL, m0, off));
            m1 = fmaxf(m1, __shfl_xor_sync(FULL, m1, off));
            m2 = fmaxf(m2, __shfl_xor_sync(FULL, m2, off));
            m3 = fmaxf(m3, __shfl_xor_sync(FULL, m3, off));
        }
        if (lane == 0) {
            red_r[warp * 4 + 0] = m0; red_r[warp * 4 + 1] = m1;
            red_r[warp * 4 + 2] = m2; red_r[warp * 4 + 3] = m3;
        }
        __syncthreads();
        if (tid < 4) {
            float m = red_r[tid];
            for (int w = 1; w < 4; w++) m = fmaxf(m, red_r[w * 4 + tid]);
            s_m[tid] = m;
        }
        __syncthreads();
        float M0 = s_m[0], M1 = s_m[1], M2 = s_m[2], M3 = s_m[3];
        float e00 = expf(v0.x - M0), e01 = expf(v0.y - M1);
        float e02 = expf(v0.z - M2), e03 = expf(v0.w - M3);
        float e10 = expf(v1.x - M0), e11 = expf(v1.y - M1);
        float e12 = expf(v1.z - M2), e13 = expf(v1.w - M3);
        *(float4*)&sc[k0 * 4]     = make_float4(e00, e01, e02, e03);
        *(float4*)&sc[k0 * 4 + 4] = make_float4(e10, e11, e12, e13);
        float t0 = e00 + e10, t1 = e01 + e11, t2 = e02 + e12, t3 = e03 + e13;
#pragma unroll
        for (int off = 16; off > 0; off >>= 1) {
            t0 += __shfl_xor_sync(FULL, t0, off);
            t1 += __shfl_xor_sync(FULL, t1, off);
            t2 += __shfl_xor_sync(FULL, t2, off);
            t3 += __shfl_xor_sync(FULL, t3, off);
        }
        if (lane == 0) {
            red_r[warp * 4 + 0] = t0; red_r[warp * 4 + 1] = t1;
            red_r[warp * 4 + 2] = t2; red_r[warp * 4 + 3] = t3;
        }
        __syncthreads();
        if (tid < 4) {
            float s = red_r[tid];
            for (int w = 1; w < 4; w++) s += red_r[w * 4 + tid];
            s_s[tid] = s;
        }
        __syncthreads();
    }

    // ---------------- p @ V (unnormalized, packed f32x2, 2-key buf) ------
    u64 ap0 = 0, ap1 = 0, ap2 = 0, ap3 = 0, ap4 = 0, ap5 = 0, ap6 = 0, ap7 = 0;
    {
        float4 vr[2][2];
#pragma unroll
        for (int u = 0; u < 2; u++) {
            int w = base + u;
            const float* p = (w < 2047) ? (vbase + (size_t)(w + 1) * 128) : vnew;
            vr[0][u] = *(const float4*)(p + lane * 4);
        }
        for (int j0 = 0; j0 < 64; j0 += 2) {
            int cur = (j0 >> 1) & 1;
            if (j0 + 2 < 64) {
#pragma unroll
                for (int u = 0; u < 2; u++) {
                    int w = base + j0 + 2 + u;
                    const float* p = (w < 2047) ? (vbase + (size_t)(w + 1) * 128) : vnew;
                    vr[cur ^ 1][u] = *(const float4*)(p + lane * 4);
                }
            }
#pragma unroll
            for (int u = 0; u < 2; u++) {
                float4 v4 = vr[cur][u];
                float4 pv = *(const float4*)&sc[(lbase + j0 + u) * 4];  // broadcast
                u64 vx = pk2(v4.x, v4.y);
                u64 vz = pk2(v4.z, v4.w);
                u64 pp;
                pp = pk2(pv.x, pv.x); ap0 = ffma2(pp, vx, ap0); ap1 = ffma2(pp, vz, ap1);
                pp = pk2(pv.y, pv.y); ap2 = ffma2(pp, vx, ap2); ap3 = ffma2(pp, vz, ap3);
                pp = pk2(pv.z, pv.z); ap4 = ffma2(pp, vx, ap4); ap5 = ffma2(pp, vz, ap5);
                pp = pk2(pv.w, pv.w); ap6 = ffma2(pp, vx, ap6); ap7 = ffma2(pp, vz, ap7);
            }
        }
    }

    // unpack accumulators to smem: outp[warp][head][128]
    {
        float f0, f1, f2, f3;
        upk2(ap0, f0, f1); upk2(ap1, f2, f3);
        *(float4*)&outp[warp * 512 + 0 * 128 + lane * 4] = make_float4(f0, f1, f2, f3);
        upk2(ap2, f0, f1); upk2(ap3, f2, f3);
        *(float4*)&outp[warp * 512 + 1 * 128 + lane * 4] = make_float4(f0, f1, f2, f3);
        upk2(ap4, f0, f1); upk2(ap5, f2, f3);
        *(float4*)&outp[warp * 512 + 2 * 128 + lane * 4] = make_float4(f0, f1, f2, f3);
        upk2(ap6, f0, f1); upk2(ap7, f2, f3);
        *(float4*)&outp[warp * 512 + 3 * 128 + lane * 4] = make_float4(f0, f1, f2, f3);
    }
    __syncthreads();

    // write partials: [bh][split][g][128]
    const size_t pb = (bh * 8 + spl) * 4;
    for (int oi = tid; oi < 512; oi += 128) {
        float s = outp[oi] + outp[512 + oi] + outp[1024 + oi] + outp[1536 + oi];
        g_pout[(pb + (oi >> 7)) * 128 + (oi & 127)] = s;
    }
    if (tid < 4) {
        g_pm[pb + tid] = s_m[tid];
        g_ps[pb + tid] = s_s[tid];
    }
}

// ------------------------------------------------------------------
// Combine 8 split partials. grid (64, 8), 512 threads.
// ------------------------------------------------------------------
__global__ __launch_bounds__(512) void attn_combine()
{
    const int b  = blockIdx.x;
    const int kh = blockIdx.y;
    const int tid = threadIdx.x;        // 0..511
    const int g = tid >> 7;
    const int d = tid & 127;

    const size_t bh = (size_t)(b * 8 + kh);
    const size_t pb = bh * 32;          // [split(8)][g(4)]

    float m[8];
#pragma unroll
    for (int s = 0; s < 8; s++) m[s] = g_pm[pb + s * 4 + g];
    float M = m[0];
#pragma unroll
    for (int s = 1; s < 8; s++) M = fmaxf(M, m[s]);
    float denom = 0.f, val = 0.f;
#pragma unroll
    for (int s = 0; s < 8; s++) {
        float w = expf(m[s] - M);
        denom += g_ps[pb + s * 4 + g] * w;
        val   += g_pout[(pb + s * 4 + g) * 128 + d] * w;
    }
    g_attn[bh * 512 + tid] = val / denom;
}

// ------------------------------------------------------------------
// Reduce O split-K partials (16)
// ------------------------------------------------------------------
__global__ __launch_bounds__(256) void reduce_o()
{
    int idx = blockIdx.x * 256 + threadIdx.x;   // < 262144
    float s = 0.f;
#pragma unroll
    for (int sp = 0; sp < 16; sp++) s += g_opart[(size_t)sp * 262144 + idx];
    g_obuf[idx] = s;
}

// ------------------------------------------------------------------
// Reduce gate partials (32) + bias + sigmoid + residual
// ------------------------------------------------------------------
__global__ __launch_bounds__(256) void reduce_gate(
    const float* __restrict__ gb, const float* __restrict__ x, float* __restrict__ out)
{
    int idx = blockIdx.x * 256 + threadIdx.x;   // < 262144
    int i = idx & 4095;
    float s = gb[i];
#pragma unroll
    for (int sp = 0; sp < 32; sp++) s += g_gpart[(size_t)sp * 262144 + idx];
    float g = 1.0f / (1.0f + expf(-s));
    out[idx] = x[idx] + g * g_obuf[idx];
}

// ------------------------------------------------------------------
// Launch
// ------------------------------------------------------------------
extern "C" void kernel_launch(void* const* d_in, const int* in_sizes, int n_in,
                              void* d_out, int out_size)
{
    const float* x  = (const float*)d_in[0];
    const float* kc = (const float*)d_in[1];
    const float* vc = (const float*)d_in[2];
    const float* Wq = (const float*)d_in[3];
    const float* Wk = (const float*)d_in[4];
    const float* Wv = (const float*)d_in[5];
    const float* Wo = (const float*)d_in[6];
    const float* gw = (const float*)d_in[7];
    const float* gb = (const float*)d_in[8];
    const int*   pp = (const int*)d_in[9];
    float* out = (float*)d_out;

    rope_tab<<<1, 64>>>(pp);

    // Fused QKV: n-tiles 24, split-K 16
    gemm_v2<<<dim3(24, 16), 256>>>(0, x, Wq, Wk, Wv, 4096, 6144, 256);
    reduce_qkv_rope<<<768, 256>>>();

    // Split-KV attention (8 splits) + combine
    attn_split<<<dim3(64, 8, 8), 128>>>(kc, vc);
    attn_combine<<<dim3(64, 8), 512>>>();

    // O projection: n-tiles 16, split-K 16
    gemm_v2<<<dim3(16, 16), 256>>>(1, x, Wo, nullptr, nullptr, 4096, 4096, 256);
    reduce_o<<<1024, 256>>>();

    // Gate: n-tiles 16, split-K 32
    gemm_v2<<<dim3(16, 32), 256>>>(2, x, gw, nullptr, nullptr, 8192, 4096, 256);
    reduce_gate<<<1024, 256>>>(gb, x, out);
}

// round 15
// speedup vs baseline: 1.1996x; 1.0083x over previous
#include <cuda_runtime.h>
#include <cstdint>
#include <math.h>

// Shapes: B=64, D=4096, H=32, HKV=8, DH=128, W=2048, G=4
typedef unsigned long long u64;

// ------------------------------------------------------------------
// Scratch (device globals; no allocation allowed)
// ------------------------------------------------------------------
__device__ float g_qkv_part[16 * 64 * 6144];  // split-K partials, fused QKV
__device__ float g_q[64 * 4096];              // q after RoPE (scaled by 1/sqrt(DH))
__device__ float g_knew[64 * 1024];           // k_new after RoPE
__device__ float g_vnew[64 * 1024];
__device__ float g_attn[64 * 4096];           // attention output (pre W_o)
__device__ float g_opart[16 * 64 * 4096];     // split-K partials, O proj
__device__ float g_obuf[64 * 4096];           // out = attn @ W_o^T
__device__ float g_gpart[32 * 64 * 4096];     // split-K partials, gate
__device__ float g_rc[64];                    // RoPE cos table (fp64-exact)
__device__ float g_rs[64];                    // RoPE sin table
// split-KV attention partials: [b*8+kh][split(8)][g(4)][128]
__device__ float g_pout[64 * 8 * 8 * 4 * 128];
__device__ float g_pm[64 * 8 * 8 * 4];        // local max
__device__ float g_ps[64 * 8 * 8 * 4];        // local exp-sum

// ------------------------------------------------------------------
// packed f32x2 helpers
// ------------------------------------------------------------------
__device__ __forceinline__ u64 pk2(float x, float y) {
    u64 r; asm("mov.b64 %0, {%1, %2};" : "=l"(r) : "f"(x), "f"(y)); return r;
}
__device__ __forceinline__ void upk2(u64 v, float& x, float& y) {
    asm("mov.b64 {%0, %1}, %2;" : "=f"(x), "=f"(y) : "l"(v));
}
__device__ __forceinline__ u64 ffma2(u64 a, u64 b, u64 c) {
    u64 d; asm("fma.rn.f32x2 %0, %1, %2, %3;" : "=l"(d) : "l"(a), "l"(b), "l"(c)); return d;
}

// ------------------------------------------------------------------
// GEMM v2 (unchanged): C[64,N] = A[64,Ktot] @ B[N,Ktot]^T
// ------------------------------------------------------------------
__global__ __launch_bounds__(256, 2) void gemm_v2(
    int mode, const float* __restrict__ x,
    const float* __restrict__ B0, const float* __restrict__ B1, const float* __restrict__ B2,
    int KtotB, int N, int Kc)
{
    __shared__ float As[2][16][68];
    __shared__ float Bs[2][16][260];

    const int tid = threadIdx.x;
    const int n0  = blockIdx.x * 256;
    const int sp  = blockIdx.y;
    const int kb  = sp * Kc;

    const float* Abase;
    int koff = kb;
    if (mode == 0) Abase = x;
    else if (mode == 1) Abase = g_attn;
    else { if (kb < 4096) Abase = x; else { Abase = g_obuf; koff = kb - 4096; } }

    const float* Bb = B0;
    int nr = n0;
    if (mode == 0 && n0 >= 4096) {
        if (n0 < 5120) { Bb = B1; nr = n0 - 4096; }
        else           { Bb = B2; nr = n0 - 5120; }
    }

    float* Cp = (mode == 0) ? g_qkv_part : (mode == 1) ? g_opart : g_gpart;

    const int lr  = tid >> 2;
    const int lk4 = (tid & 3) << 2;
    const float* arow  = Abase + (size_t)lr * 4096 + koff + lk4;
    const float* brow0 = Bb + (size_t)(nr + lr +   0) * KtotB + kb + lk4;
    const float* brow1 = Bb + (size_t)(nr + lr +  64) * KtotB + kb + lk4;
    const float* brow2 = Bb + (size_t)(nr + lr + 128) * KtotB + kb + lk4;
    const float* brow3 = Bb + (size_t)(nr + lr + 192) * KtotB + kb + lk4;

    const int m0 = (tid >> 5) << 3;
    const int nA = (tid & 31) << 2;
    const int nB = nA + 128;

    u64 cA[8][2], cB[8][2];
#pragma unroll
    for (int m = 0; m < 8; m++) { cA[m][0]=0; cA[m][1]=0; cB[m][0]=0; cB[m][1]=0; }

    const int T = Kc >> 4;
    float4 av, bv0, bv1, bv2, bv3;

    av  = *(const float4*)(arow);
    bv0 = *(const float4*)(brow0);
    bv1 = *(const float4*)(brow1);
    bv2 = *(const float4*)(brow2);
    bv3 = *(const float4*)(brow3);
    As[0][lk4+0][lr]=av.x; As[0][lk4+1][lr]=av.y; As[0][lk4+2][lr]=av.z; As[0][lk4+3][lr]=av.w;
    Bs[0][lk4+0][lr    ]=bv0.x; Bs[0][lk4+1][lr    ]=bv0.y; Bs[0][lk4+2][lr    ]=bv0.z; Bs[0][lk4+3][lr    ]=bv0.w;
    Bs[0][lk4+0][lr+ 64]=bv1.x; Bs[0][lk4+1][lr+ 64]=bv1.y; Bs[0][lk4+2][lr+ 64]=bv1.z; Bs[0][lk4+3][lr+ 64]=bv1.w;
    Bs[0][lk4+0][lr+128]=bv2.x; Bs[0][lk4+1][lr+128]=bv2.y; Bs[0][lk4+2][lr+128]=bv2.z; Bs[0][lk4+3][lr+128]=bv2.w;
    Bs[0][lk4+0][lr+192]=bv3.x; Bs[0][lk4+1][lr+192]=bv3.y; Bs[0][lk4+2][lr+192]=bv3.z; Bs[0][lk4+3][lr+192]=bv3.w;
    __syncthreads();

    for (int t = 0; t < T; t++) {
        const int cur = t & 1;
        if (t + 1 < T) {
            const int ko = (t + 1) << 4;
            av  = *(const float4*)(arow  + ko);
            bv0 = *(const float4*)(brow0 + ko);
            bv1 = *(const float4*)(brow1 + ko);
            bv2 = *(const float4*)(brow2 + ko);
            bv3 = *(const float4*)(brow3 + ko);
        }
#pragma unroll
        for (int k = 0; k < 16; k++) {
            ulonglong2 bA  = *(const ulonglong2*)&Bs[cur][k][nA];
            ulonglong2 bBv = *(const ulonglong2*)&Bs[cur][k][nB];
            float4 a0 = *(const float4*)&As[cur][k][m0];
            float4 a1 = *(const float4*)&As[cur][k][m0 + 4];
            u64 s;
            s = pk2(a0.x, a0.x);
            cA[0][0]=ffma2(s,bA.x,cA[0][0]); cA[0][1]=ffma2(s,bA.y,cA[0][1]);
            cB[0][0]=ffma2(s,bBv.x,cB[0][0]); cB[0][1]=ffma2(s,bBv.y,cB[0][1]);
            s = pk2(a0.y, a0.y);
            cA[1][0]=ffma2(s,bA.x,cA[1][0]); cA[1][1]=ffma2(s,bA.y,cA[1][1]);
            cB[1][0]=ffma2(s,bBv.x,cB[1][0]); cB[1][1]=ffma2(s,bBv.y,cB[1][1]);
            s = pk2(a0.z, a0.z);
            cA[2][0]=ffma2(s,bA.x,cA[2][0]); cA[2][1]=ffma2(s,bA.y,cA[2][1]);
            cB[2][0]=ffma2(s,bBv.x,cB[2][0]); cB[2][1]=ffma2(s,bBv.y,cB[2][1]);
            s = pk2(a0.w, a0.w);
            cA[3][0]=ffma2(s,bA.x,cA[3][0]); cA[3][1]=ffma2(s,bA.y,cA[3][1]);
            cB[3][0]=ffma2(s,bBv.x,cB[3][0]); cB[3][1]=ffma2(s,bBv.y,cB[3][1]);
            s = pk2(a1.x, a1.x);
            cA[4][0]=ffma2(s,bA.x,cA[4][0]); cA[4][1]=ffma2(s,bA.y,cA[4][1]);
            cB[4][0]=ffma2(s,bBv.x,cB[4][0]); cB[4][1]=ffma2(s,bBv.y,cB[4][1]);
            s = pk2(a1.y, a1.y);
            cA[5][0]=ffma2(s,bA.x,cA[5][0]); cA[5][1]=ffma2(s,bA.y,cA[5][1]);
            cB[5][0]=ffma2(s,bBv.x,cB[5][0]); cB[5][1]=ffma2(s,bBv.y,cB[5][1]);
            s = pk2(a1.z, a1.z);
            cA[6][0]=ffma2(s,bA.x,cA[6][0]); cA[6][1]=ffma2(s,bA.y,cA[6][1]);
            cB[6][0]=ffma2(s,bBv.x,cB[6][0]); cB[6][1]=ffma2(s,bBv.y,cB[6][1]);
            s = pk2(a1.w, a1.w);
            cA[7][0]=ffma2(s,bA.x,cA[7][0]); cA[7][1]=ffma2(s,bA.y,cA[7][1]);
            cB[7][0]=ffma2(s,bBv.x,cB[7][0]); cB[7][1]=ffma2(s,bBv.y,cB[7][1]);
        }
        if (t + 1 < T) {
            const int nb = cur ^ 1;
            As[nb][lk4+0][lr]=av.x; As[nb][lk4+1][lr]=av.y; As[nb][lk4+2][lr]=av.z; As[nb][lk4+3][lr]=av.w;
            Bs[nb][lk4+0][lr    ]=bv0.x; Bs[nb][lk4+1][lr    ]=bv0.y; Bs[nb][lk4+2][lr    ]=bv0.z; Bs[nb][lk4+3][lr    ]=bv0.w;
            Bs[nb][lk4+0][lr+ 64]=bv1.x; Bs[nb][lk4+1][lr+ 64]=bv1.y; Bs[nb][lk4+2][lr+ 64]=bv1.z; Bs[nb][lk4+3][lr+ 64]=bv1.w;
            Bs[nb][lk4+0][lr+128]=bv2.x; Bs[nb][lk4+1][lr+128]=bv2.y; Bs[nb][lk4+2][lr+128]=bv2.z; Bs[nb][lk4+3][lr+128]=bv2.w;
            Bs[nb][lk4+0][lr+192]=bv3.x; Bs[nb][lk4+1][lr+192]=bv3.y; Bs[nb][lk4+2][lr+192]=bv3.z; Bs[nb][lk4+3][lr+192]=bv3.w;
            __syncthreads();
        }
    }

    {
        float* base = Cp + ((size_t)sp * 64) * N + n0;
#pragma unroll
        for (int m = 0; m < 8; m++) {
            float f0, f1, f2, f3;
            upk2(cA[m][0], f0, f1); upk2(cA[m][1], f2, f3);
            *(float4*)(base + (size_t)(m0 + m) * N + nA) = make_float4(f0, f1, f2, f3);
            upk2(cB[m][0], f0, f1); upk2(cB[m][1], f2, f3);
            *(float4*)(base + (size_t)(m0 + m) * N + nB) = make_float4(f0, f1, f2, f3);
        }
    }
}

// ------------------------------------------------------------------
// RoPE table (fp64-exact, once)
// ------------------------------------------------------------------
__global__ void rope_tab(const int* __restrict__ posp)
{
    int i = threadIdx.x;   // 0..63
    int praw = *posp;
    int pos = praw;
    if (pos < 0 || pos > (1 << 26)) {
        float pf = __int_as_float(praw);
        pos = (int)pf;
    }
    double inv = pow(10000.0, -(double)(2 * i) / 128.0);
    double sn, cn;
    sincos((double)pos * inv, &sn, &cn);
    g_rc[i] = (float)cn;
    g_rs[i] = (float)sn;
}

// ------------------------------------------------------------------
// Reduce QKV split-K partials (16) + RoPE (table lookup).
// ------------------------------------------------------------------
__global__ __launch_bounds__(256) void reduce_qkv_rope()
{
    int idx = blockIdx.x * 256 + threadIdx.x;    // pair index, < 196608
    int b = idx / 3072;
    int col = (idx - b * 3072) * 2;

    const float* p = g_qkv_part + (size_t)b * 6144 + col;
    float s0 = 0.f, s1 = 0.f;
#pragma unroll
    for (int s = 0; s < 16; s++) {
        s0 += p[(size_t)s * 64 * 6144];
        s1 += p[(size_t)s * 64 * 6144 + 1];
    }

    const float qscale = 0.08838834764831845f;   // 1/sqrt(128)

    if (col < 5120) {
        int di = (col & 127) >> 1;
        float c = g_rc[di], s = g_rs[di];
        float o0 = s0 * c - s1 * s;
        float o1 = s0 * s + s1 * c;
        if (col < 4096) {
            g_q[(size_t)b * 4096 + col]     = o0 * qscale;
            g_q[(size_t)b * 4096 + col + 1] = o1 * qscale;
        } else {
            g_knew[(size_t)b * 1024 + (col - 4096)]     = o0;
            g_knew[(size_t)b * 1024 + (col - 4096) + 1] = o1;
        }
    } else {
        g_vnew[(size_t)b * 1024 + (col - 5120)]     = s0;
        g_vnew[(size_t)b * 1024 + (col - 5120) + 1] = s1;
    }
}

// ------------------------------------------------------------------
// Per-key score: 4 dots + 6-shuffle 4-head reduction + store
// ------------------------------------------------------------------
__device__ __forceinline__ void score_one(
    float4 k4, const float4& q0, const float4& q1, const float4& q2, const float4& q3,
    bool lo16, bool b8, int lane, float* dst4)   // dst4 = &sc[key*4]
{
    const unsigned FULL = 0xffffffffu;
    float p0 = q0.x * k4.x + q0.y * k4.y + q0.z * k4.z + q0.w * k4.w;
    float p1 = q1.x * k4.x + q1.y * k4.y + q1.z * k4.z + q1.w * k4.w;
    float p2 = q2.x * k4.x + q2.y * k4.y + q2.z * k4.z + q2.w * k4.w;
    float p3 = q3.x * k4.x + q3.y * k4.y + q3.z * k4.z + q3.w * k4.w;
    float xa = lo16 ? p2 : p0;
    float ya = __shfl_xor_sync(FULL, xa, 16);
    float pA = lo16 ? (p0 + ya) : (p2 + ya);
    float xb = lo16 ? p3 : p1;
    float yb = __shfl_xor_sync(FULL, xb, 16);
    float pB = lo16 ? (p1 + yb) : (p3 + yb);
    float xc = b8 ? pA : pB;
    float yc = __shfl_xor_sync(FULL, xc, 8);
    float pC = b8 ? (pB + yc) : (pA + yc);
    pC += __shfl_xor_sync(FULL, pC, 4);
    pC += __shfl_xor_sync(FULL, pC, 2);
    pC += __shfl_xor_sync(FULL, pC, 1);
    if ((lane & 7) == 0) dst4[lane >> 3] = pC;
}

// ------------------------------------------------------------------
// Per-key pV accumulate (packed f32x2)
// ------------------------------------------------------------------
__device__ __forceinline__ void pv_one(
    float4 v4, const float* pvp,   // pvp = &sc[key*4]
    u64& ap0, u64& ap1, u64& ap2, u64& ap3,
    u64& ap4, u64& ap5, u64& ap6, u64& ap7)
{
    float4 pv = *(const float4*)pvp;   // broadcast LDS.128
    u64 vx = pk2(v4.x, v4.y);
    u64 vz = pk2(v4.z, v4.w);
    u64 pp;
    pp = pk2(pv.x, pv.x); ap0 = ffma2(pp, vx, ap0); ap1 = ffma2(pp, vz, ap1);
    pp = pk2(pv.y, pv.y); ap2 = ffma2(pp, vx, ap2); ap3 = ffma2(pp, vz, ap3);
    pp = pk2(pv.z, pv.z); ap4 = ffma2(pp, vx, ap4); ap5 = ffma2(pp, vz, ap5);
    pp = pk2(pv.w, pv.w); ap6 = ffma2(pp, vx, ap6); ap7 = ffma2(pp, vz, ap7);
}

// ------------------------------------------------------------------
// Split-KV attention v5: grid (64, 8, 8), 128 threads (4 warps).
// 256 keys/CTA, 64/warp. Clean-path warps (2047/2048 of all warps)
// stream with a marching pointer + immediate offsets (no per-load
// select/IMAD); only the single boundary warp takes the select path.
// ------------------------------------------------------------------
__global__ __launch_bounds__(128, 10) void attn_split(
    const float* __restrict__ kc, const float* __restrict__ vc)
{
    __shared__ float sc[256 * 4];      // [key][head]
    __shared__ float outp[4 * 512];    // [warp][head][128]
    __shared__ float red_r[4 * 4];     // [warp][head]
    __shared__ float s_m[4];
    __shared__ float s_s[4];

    const int tid  = threadIdx.x;
    const int b    = blockIdx.x;
    const int kh   = blockIdx.y;
    const int spl  = blockIdx.z;
    const int warp = tid >> 5;
    const int lane = tid & 31;
    const unsigned FULL = 0xffffffffu;

    const float* qp = g_q + (size_t)b * 4096 + kh * 512;   // pre-scaled
    float4 q0 = *(const float4*)(qp + 0 * 128 + lane * 4);
    float4 q1 = *(const float4*)(qp + 1 * 128 + lane * 4);
    float4 q2 = *(const float4*)(qp + 2 * 128 + lane * 4);
    float4 q3 = *(const float4*)(qp + 3 * 128 + lane * 4);

    const size_t bh = (size_t)(b * 8 + kh);
    const float* kbase = kc + bh * (2048 * 128);
    const float* vbase = vc + bh * (2048 * 128);
    const float* knew  = g_knew + bh * 128;
    const float* vnew  = g_vnew + bh * 128;

    const int base  = spl * 256 + warp * 64;   // first key of this warp
    const int lbase = warp * 64;               // local score base
    const bool tail = (base + 64) > 2047;      // only spl=7, warp=3
    const bool lo16 = (lane < 16);
    const bool b8   = (lane & 8) != 0;

    // ---------------- score phase ----------------
    if (!tail) {
        const float4* kp = (const float4*)(kbase + (size_t)(base + 1) * 128) + lane;
        float* scp = sc + lbase * 4;
        float4 ka = kp[0], kb2 = kp[32];
        for (int j = 0; j < 64; j += 2) {
            float4 na = make_float4(0.f, 0.f, 0.f, 0.f), nb = na;
            if (j + 2 < 64) { na = kp[64]; nb = kp[96]; }
            score_one(ka,  q0, q1, q2, q3, lo16, b8, lane, scp);
            score_one(kb2, q0, q1, q2, q3, lo16, b8, lane, scp + 4);
            ka = na; kb2 = nb; kp += 64; scp += 8;
        }
    } else {
        float4 kr[2][2];
#pragma unroll
        for (int u = 0; u < 2; u++) {
            int w = base + u;
            const float* p = (w < 2047) ? (kbase + (size_t)(w + 1) * 128) : knew;
            kr[0][u] = *(const float4*)(p + lane * 4);
        }
        for (int j0 = 0; j0 < 64; j0 += 2) {
            int cur = (j0 >> 1) & 1;
            if (j0 + 2 < 64) {
#pragma unroll
                for (int u = 0; u < 2; u++) {
                    int w = base + j0 + 2 + u;
                    const float* p = (w < 2047) ? (kbase + (size_t)(w + 1) * 128) : knew;
                    kr[cur ^ 1][u] = *(const float4*)(p + lane * 4);
                }
            }
            score_one(kr[cur][0], q0, q1, q2, q3, lo16, b8, lane, &sc[(lbase + j0) * 4]);
            score_one(kr[cur][1], q0, q1, q2, q3, lo16, b8, lane, &sc[(lbase + j0 + 1) * 4]);
        }
    }
    __syncthreads();

    // ---------------- single-pass local softmax ----------------
    {
        const int k0 = tid * 2;            // thread owns keys k0, k0+1
        float4 v0 = *(const float4*)&sc[k0 * 4];
        float4 v1 = *(const float4*)&sc[k0 * 4 + 4];
        float m0 = fmaxf(v0.x, v1.x), m1 = fmaxf(v0.y, v1.y);
        float m2 = fmaxf(v0.z, v1.z), m3 = fmaxf(v0.w, v1.w);
#pragma unroll
        for (int off = 16; off > 0; off >>= 1) {
            m0 = fmaxf(m0, __shfl_xor_sync(FULL, m0, off));
            m1 = fmaxf(m1, __shfl_xor_sync(FULL, m1, off));
            m2 = fmaxf(m2, __shfl_xor_sync(FULL, m2, off));
            m3 = fmaxf(m3, __shfl_xor_sync(FULL, m3, off));
        }
        if (lane == 0) {
            red_r[warp * 4 + 0] = m0; red_r[warp * 4 + 1] = m1;
            red_r[warp * 4 + 2] = m2; red_r[warp * 4 + 3] = m3;
        }
        __syncthreads();
        if (tid < 4) {
            float m = red_r[tid];
            for (int w = 1; w < 4; w++) m = fmaxf(m, red_r[w * 4 + tid]);
            s_m[tid] = m;
        }
        __syncthreads();
        float M0 = s_m[0], M1 = s_m[1], M2 = s_m[2], M3 = s_m[3];
        float e00 = expf(v0.x - M0), e01 = expf(v0.y - M1);
        float e02 = expf(v0.z - M2), e03 = expf(v0.w - M3);
        float e10 = expf(v1.x - M0), e11 = expf(v1.y - M1);
        float e12 = expf(v1.z - M2), e13 = expf(v1.w - M3);
        *(float4*)&sc[k0 * 4]     = make_float4(e00, e01, e02, e03);
        *(float4*)&sc[k0 * 4 + 4] = make_float4(e10, e11, e12, e13);
        float t0 = e00 + e10, t1 = e01 + e11, t2 = e02 + e12, t3 = e03 + e13;
#pragma unroll
        for (int off = 16; off > 0; off >>= 1) {
            t0 += __shfl_xor_sync(FULL, t0, off);
            t1 += __shfl_xor_sync(FULL, t1, off);
            t2 += __shfl_xor_sync(FULL, t2, off);
            t3 += __shfl_xor_sync(FULL, t3, off);
        }
        if (lane == 0) {
            red_r[warp * 4 + 0] = t0; red_r[warp * 4 + 1] = t1;
            red_r[warp * 4 + 2] = t2; red_r[warp * 4 + 3] = t3;
        }
        __syncthreads();
        if (tid < 4) {
            float s = red_r[tid];
            for (int w = 1; w < 4; w++) s += red_r[w * 4 + tid];
            s_s[tid] = s;
        }
        __syncthreads();
    }

    // ---------------- p @ V (unnormalized, packed f32x2) ----------------
    u64 ap0 = 0, ap1 = 0, ap2 = 0, ap3 = 0, ap4 = 0, ap5 = 0, ap6 = 0, ap7 = 0;
    if (!tail) {
        const float4* vp = (const float4*)(vbase + (size_t)(base + 1) * 128) + lane;
        const float* pvp = sc + lbase * 4;
        float4 va = vp[0], vb = vp[32];
        for (int j = 0; j < 64; j += 2) {
            float4 na = make_float4(0.f, 0.f, 0.f, 0.f), nb = na;
            if (j + 2 < 64) { na = vp[64]; nb = vp[96]; }
            pv_one(va, pvp,     ap0, ap1, ap2, ap3, ap4, ap5, ap6, ap7);
            pv_one(vb, pvp + 4, ap0, ap1, ap2, ap3, ap4, ap5, ap6, ap7);
            va = na; vb = nb; vp += 64; pvp += 8;
        }
    } else {
        float4 vr[2][2];
#pragma unroll
        for (int u = 0; u < 2; u++) {
            int w = base + u;
            const float* p = (w < 2047) ? (vbase + (size_t)(w + 1) * 128) : vnew;
            vr[0][u] = *(const float4*)(p + lane * 4);
        }
        for (int j0 = 0; j0 < 64; j0 += 2) {
            int cur = (j0 >> 1) & 1;
            if (j0 + 2 < 64) {
#pragma unroll
                for (int u = 0; u < 2; u++) {
                    int w = base + j0 + 2 + u;
                    const float* p = (w < 2047) ? (vbase + (size_t)(w + 1) * 128) : vnew;
                    vr[cur ^ 1][u] = *(const float4*)(p + lane * 4);
                }
            }
            pv_one(vr[cur][0], &sc[(lbase + j0) * 4],     ap0, ap1, ap2, ap3, ap4, ap5, ap6, ap7);
            pv_one(vr[cur][1], &sc[(lbase + j0 + 1) * 4], ap0, ap1, ap2, ap3, ap4, ap5, ap6, ap7);
        }
    }

    // unpack accumulators to smem: outp[warp][head][128]
    {
        float f0, f1, f2, f3;
        upk2(ap0, f0, f1); upk2(ap1, f2, f3);
        *(float4*)&outp[warp * 512 + 0 * 128 + lane * 4] = make_float4(f0, f1, f2, f3);
        upk2(ap2, f0, f1); upk2(ap3, f2, f3);
        *(float4*)&outp[warp * 512 + 1 * 128 + lane * 4] = make_float4(f0, f1, f2, f3);
        upk2(ap4, f0, f1); upk2(ap5, f2, f3);
        *(float4*)&outp[warp * 512 + 2 * 128 + lane * 4] = make_float4(f0, f1, f2, f3);
        upk2(ap6, f0, f1); upk2(ap7, f2, f3);
        *(float4*)&outp[warp * 512 + 3 * 128 + lane * 4] = make_float4(f0, f1, f2, f3);
    }
    __syncthreads();

    // write partials: [bh][split][g][128]
    const size_t pb = (bh * 8 + spl) * 4;
    for (int oi = tid; oi < 512; oi += 128) {
        float s = outp[oi] + outp[512 + oi] + outp[1024 + oi] + outp[1536 + oi];
        g_pout[(pb + (oi >> 7)) * 128 + (oi & 127)] = s;
    }
    if (tid < 4) {
        g_pm[pb + tid] = s_m[tid];
        g_ps[pb + tid] = s_s[tid];
    }
}

// ------------------------------------------------------------------
// Combine 8 split partials. grid (64, 8), 512 threads.
// ------------------------------------------------------------------
__global__ __launch_bounds__(512) void attn_combine()
{
    const int b  = blockIdx.x;
    const int kh = blockIdx.y;
    const int tid = threadIdx.x;        // 0..511
    const int g = tid >> 7;
    const int d = tid & 127;

    const size_t bh = (size_t)(b * 8 + kh);
    const size_t pb = bh * 32;          // [split(8)][g(4)]

    float m[8];
#pragma unroll
    for (int s = 0; s < 8; s++) m[s] = g_pm[pb + s * 4 + g];
    float M = m[0];
#pragma unroll
    for (int s = 1; s < 8; s++) M = fmaxf(M, m[s]);
    float denom = 0.f, val = 0.f;
#pragma unroll
    for (int s = 0; s < 8; s++) {
        float w = expf(m[s] - M);
        denom += g_ps[pb + s * 4 + g] * w;
        val   += g_pout[(pb + s * 4 + g) * 128 + d] * w;
    }
    g_attn[bh * 512 + tid] = val / denom;
}

// ------------------------------------------------------------------
// Reduce O split-K partials (16)
// ------------------------------------------------------------------
__global__ __launch_bounds__(256) void reduce_o()
{
    int idx = blockIdx.x * 256 + threadIdx.x;   // < 262144
    float s = 0.f;
#pragma unroll
    for (int sp = 0; sp < 16; sp++) s += g_opart[(size_t)sp * 262144 + idx];
    g_obuf[idx] = s;
}

// ------------------------------------------------------------------
// Reduce gate partials (32) + bias + sigmoid + residual
// ------------------------------------------------------------------
__global__ __launch_bounds__(256) void reduce_gate(
    const float* __restrict__ gb, const float* __restrict__ x, float* __restrict__ out)
{
    int idx = blockIdx.x * 256 + threadIdx.x;   // < 262144
    int i = idx & 4095;
    float s = gb[i];
#pragma unroll
    for (int sp = 0; sp < 32; sp++) s += g_gpart[(size_t)sp * 262144 + idx];
    float g = 1.0f / (1.0f + expf(-s));
    out[idx] = x[idx] + g * g_obuf[idx];
}

// ------------------------------------------------------------------
// Launch
// ------------------------------------------------------------------
extern "C" void kernel_launch(void* const* d_in, const int* in_sizes, int n_in,
                              void* d_out, int out_size)
{
    const float* x  = (const float*)d_in[0];
    const float* kc = (const float*)d_in[1];
    const float* vc = (const float*)d_in[2];
    const float* Wq = (const float*)d_in[3];
    const float* Wk = (const float*)d_in[4];
    const float* Wv = (const float*)d_in[5];
    const float* Wo = (const float*)d_in[6];
    const float* gw = (const float*)d_in[7];
    const float* gb = (const float*)d_in[8];
    const int*   pp = (const int*)d_in[9];
    float* out = (float*)d_out;

    rope_tab<<<1, 64>>>(pp);

    // Fused QKV: n-tiles 24, split-K 16
    gemm_v2<<<dim3(24, 16), 256>>>(0, x, Wq, Wk, Wv, 4096, 6144, 256);
    reduce_qkv_rope<<<768, 256>>>();

    // Split-KV attention (8 splits) + combine
    attn_split<<<dim3(64, 8, 8), 128>>>(kc, vc);
    attn_combine<<<dim3(64, 8), 512>>>();

    // O projection: n-tiles 16, split-K 16
    gemm_v2<<<dim3(16, 16), 256>>>(1, x, Wo, nullptr, nullptr, 4096, 4096, 256);
    reduce_o<<<1024, 256>>>();

    // Gate: n-tiles 16, split-K 32
    gemm_v2<<<dim3(16, 32), 256>>>(2, x, gw, nullptr, nullptr, 8192, 4096, 256);
    reduce_gate<<<1024, 256>>>(gb, x, out);
}